// round 1
// baseline (speedup 1.0000x reference)
#include <cuda_runtime.h>
#include <math.h>

#define NNODES 4096
#define NCH    128
#define NELEM  10
#define NFEAT  128

// ---------------------------------------------------------------------------
// CG table registry: 19 unique (l1,l2,l3) real-CG tensors, packed into g_cg.
// ---------------------------------------------------------------------------
#define NTAB 19
__constant__ int c_tab_l[NTAB][3] = {
  {0,0,0},{0,1,1},{1,0,1},{1,1,0},{1,1,1},{1,2,1},{2,1,1},{2,2,0},{2,2,1},
  {0,2,2},{1,1,2},{1,2,2},{1,2,3},{2,0,2},{2,1,2},{2,1,3},{2,2,2},{2,2,3},{3,2,1}};
__constant__ int c_tab_off[NTAB] = {0,1,10,19,28,55,100,145,170,245,270,315,390,495,520,595,700,825,1000};
#define CG_TOTAL 1105

#define OFF_000 0
#define OFF_011 1
#define OFF_101 10
#define OFF_110 19
#define OFF_111 28
#define OFF_121 55
#define OFF_211 100
#define OFF_220 145
#define OFF_221 170
#define OFF_022 245
#define OFF_112 270
#define OFF_122 315
#define OFF_123 390
#define OFF_202 495
#define OFF_212 520
#define OFF_213 595
#define OFF_222 700
#define OFF_223 825
#define OFF_321 1000

__device__ float  g_cg[CG_TOTAL];
__device__ float4 g_B[NNODES * NCH];   // per (node,channel): {B0, B1x, B1y, B1z}

// ---------------------------------------------------------------------------
// Setup: compute real CG coefficients (e3nn convention) on device, fp32.
// Mirrors the reference _su2_cg / _c2r / real_cg exactly.
// ---------------------------------------------------------------------------
__device__ __forceinline__ float ffact(int n) {
  const float F[11] = {1.f,1.f,2.f,6.f,24.f,120.f,720.f,5040.f,40320.f,362880.f,3628800.f};
  return F[n];
}

__device__ float su2cg(int j1,int m1,int j2,int m2,int j3,int m3) {
  if (m1 + m2 != m3) return 0.f;
  int vmin = max(max(-j1 + j2 + m3, -j1 + m1), 0);
  int vmax = min(min(j2 + j3 + m1, j3 - j1 + j2), j3 + m3);
  if (vmax < vmin) return 0.f;
  float C = sqrtf((2.f*j3 + 1.f) * ffact(j3+j1-j2) * ffact(j3-j1+j2) * ffact(j1+j2-j3)
                  * ffact(j3+m3) * ffact(j3-m3)
                  / (ffact(j1+j2+j3+1) * ffact(j1-m1) * ffact(j1+m1)
                     * ffact(j2-m2) * ffact(j2+m2)));
  float S = 0.f;
  for (int v = vmin; v <= vmax; v++) {
    float t = ffact(j2+j3+m1-v) * ffact(j1-m1+v)
            / (ffact(v) * ffact(j3-j1+j2-v) * ffact(j3+m3-v) * ffact(v+j1-j2-m3));
    S += ((v + j2 + m2) & 1) ? -t : t;
  }
  return C * S;
}

// c2r(l)[r][c], complex, including the (-i)^l global phase.
__device__ float2 c2r_e(int l, int r, int c) {
  int m = r - l;
  const float IS2 = 0.7071067811865476f;
  float re = 0.f, im = 0.f;
  if (m < 0) {
    if (c == l - m)      re = IS2;     // col l + |m|
    else if (c == l + m) im = -IS2;    // col l - |m|
  } else if (m == 0) {
    if (c == l) re = 1.f;
  } else {
    float s = (m & 1) ? -1.f : 1.f;
    if (c == l + m)      re = s * IS2;
    else if (c == l - m) im = s * IS2;
  }
  // multiply by (-i)^l
  float tr;
  switch (l & 3) {
    case 1: tr = re; re = im;  im = -tr; break;  // *( -i)
    case 2: re = -re; im = -im;          break;  // *(-1)
    case 3: tr = re; re = -im; im = tr;  break;  // *( i)
    default: break;
  }
  return make_float2(re, im);
}

__global__ void cg_setup_kernel() {
  int t  = blockIdx.x;
  int l1 = c_tab_l[t][0], l2 = c_tab_l[t][1], l3 = c_tab_l[t][2];
  int d1 = 2*l1+1, d2 = 2*l2+1, d3 = 2*l3+1;
  int nent = d1 * d2 * d3;
  float* out = g_cg + c_tab_off[t];
  for (int e = threadIdx.x; e < nent; e += blockDim.x) {
    int m    = e % d3;
    int jl   = e / d3;
    int lcol = jl % d2;
    int j    = jl / d2;
    // R[j,lcol,m] = Re sum_{i,k} Q1[i,j] Q2[k,lcol] conj(Q3[n3,m]) * su2cg(...)
    float acc = 0.f;
    for (int i = 0; i < d1; i++)
      for (int k = 0; k < d2; k++) {
        int m1 = i - l1, m2 = k - l2, m3 = m1 + m2;
        if (m3 < -l3 || m3 > l3) continue;
        float cc = su2cg(l1, m1, l2, m2, l3, m3);
        if (cc == 0.f) continue;
        float2 q1 = c2r_e(l1, i, j);
        float2 q2 = c2r_e(l2, k, lcol);
        float2 q3 = c2r_e(l3, m3 + l3, m);
        float pr = q1.x*q2.x - q1.y*q2.y;
        float pi = q1.x*q2.y + q1.y*q2.x;
        acc += cc * (pr * q3.x + pi * q3.y);  // * conj(q3), real part
      }
    out[e] = acc;
  }
}

// ---------------------------------------------------------------------------
// Contraction helpers (all dims compile-time, fully unrolled, arrays in regs)
// ---------------------------------------------------------------------------
template<int D1,int D2,int D3>
__device__ __forceinline__ void contract(const float* __restrict__ cg,
                                         const float* a, const float* b, float* t) {
#pragma unroll
  for (int k = 0; k < D3; k++) t[k] = 0.f;
#pragma unroll
  for (int i = 0; i < D1; i++)
#pragma unroll
    for (int j = 0; j < D2; j++) {
      float p = a[i] * b[j];
#pragma unroll
      for (int k = 0; k < D3; k++) t[k] = fmaf(cg[(i*D2+j)*D3+k], p, t[k]);
    }
}

template<int D1,int D2,int D3>
__device__ __forceinline__ void contract_acc(const float* __restrict__ cg,
                                             const float* a, const float* b, float* B) {
#pragma unroll
  for (int i = 0; i < D1; i++)
#pragma unroll
    for (int j = 0; j < D2; j++) {
      float p = a[i] * b[j];
#pragma unroll
      for (int k = 0; k < D3; k++) B[k] = fmaf(cg[(i*D2+j)*D3+k], p, B[k]);
    }
}

template<int D>
__device__ __forceinline__ void saxpy(float w, const float* t, float* S) {
#pragma unroll
  for (int k = 0; k < D; k++) S[k] = fmaf(w, t[k], S[k]);
}

// ---------------------------------------------------------------------------
// Phase A: per (node, channel) product basis -> B[4]
// block = node (4096 blocks), thread = channel (128)
// ---------------------------------------------------------------------------
__global__ __launch_bounds__(128)
void phaseA_kernel(const float* __restrict__ feats,
                   const float* __restrict__ w1,
                   const float* __restrict__ w2,
                   const float* __restrict__ w3,
                   const int*   __restrict__ species) {
  __shared__ float s_cg[CG_TOTAL];
  __shared__ float s_feats[NCH * 9];

  const int n = blockIdx.x;
  const int c = threadIdx.x;

  for (int i = c; i < CG_TOTAL; i += 128) s_cg[i] = g_cg[i];
  const float* fptr = feats + (size_t)n * NCH * 9;
  for (int i = c; i < NCH * 9; i += 128) s_feats[i] = fptr[i];
  __syncthreads();

  const int e = species[n];
  float A[9];
#pragma unroll
  for (int k = 0; k < 9; k++) A[k] = s_feats[c * 9 + k];

  const float* w1p = w1 + (size_t)(e * 2)  * NCH + c;
  const float* w2p = w2 + (size_t)(e * 9)  * NCH + c;
  const float* w3p = w3 + (size_t)(e * 51) * NCH + c;
#define W1(p) w1p[(p)*NCH]
#define W2(p) w2p[(p)*NCH]
#define W3(p) w3p[(p)*NCH]

  float B0 = 0.f;
  float B1[3] = {0.f, 0.f, 0.f};

  // ---- correlation order 1: PATHS1 = [0, 1] ----
  B0 = fmaf(W1(0), A[0], B0);
  {
    float w = W1(1);
#pragma unroll
    for (int k = 0; k < 3; k++) B1[k] = fmaf(w, A[1 + k], B1[k]);
  }

  // ---- correlation order 2: 9 paths ----
  { float t[1]; contract<1,1,1>(s_cg+OFF_000, A,   A,   t); B0 = fmaf(W2(0), t[0], B0); }
  { float t[3]; contract<1,3,3>(s_cg+OFF_011, A,   A+1, t); saxpy<3>(W2(1), t, B1); }
  { float t[3]; contract<3,1,3>(s_cg+OFF_101, A+1, A,   t); saxpy<3>(W2(2), t, B1); }
  { float t[1]; contract<3,3,1>(s_cg+OFF_110, A+1, A+1, t); B0 = fmaf(W2(3), t[0], B0); }
  { float t[3]; contract<3,3,3>(s_cg+OFF_111, A+1, A+1, t); saxpy<3>(W2(4), t, B1); }
  { float t[3]; contract<3,5,3>(s_cg+OFF_121, A+1, A+4, t); saxpy<3>(W2(5), t, B1); }
  { float t[3]; contract<5,3,3>(s_cg+OFF_211, A+4, A+1, t); saxpy<3>(W2(6), t, B1); }
  { float t[1]; contract<5,5,1>(s_cg+OFF_220, A+4, A+4, t); B0 = fmaf(W2(7), t[0], B0); }
  { float t[3]; contract<5,5,3>(s_cg+OFF_221, A+4, A+4, t); saxpy<3>(W2(8), t, B1); }

  // ---- correlation order 3 ----
  // Weighted sums S over T12 keys, grouped by second-stage combo (l12,l3,lo).
  float S0_00 = 0.f, S0_11 = 0.f;                               // l12 = 0
  float S1_01[3] = {0,0,0}, S1_10[3] = {0,0,0};                 // l12 = 1
  float S1_11[3] = {0,0,0}, S1_21[3] = {0,0,0};
  float S2_11[5] = {0,0,0,0,0}, S2_20[5] = {0,0,0,0,0};         // l12 = 2
  float S2_21[5] = {0,0,0,0,0};
  float S3_21[7] = {0,0,0,0,0,0,0};                             // l12 = 3

  // key 0: (0,0,0)  paths 0,1
  { float t[1]; contract<1,1,1>(s_cg+OFF_000, A, A, t);
    S0_00 = fmaf(W3(0), t[0], S0_00); S0_11 = fmaf(W3(1), t[0], S0_11); }
  // key 1: (0,1,1)  paths 2..5
  { float t[3]; contract<1,3,3>(s_cg+OFF_011, A, A+1, t);
    saxpy<3>(W3(2), t, S1_01); saxpy<3>(W3(3), t, S1_10);
    saxpy<3>(W3(4), t, S1_11); saxpy<3>(W3(5), t, S1_21); }
  // key 2: (0,2,2)  paths 6..8
  { float t[5]; contract<1,5,5>(s_cg+OFF_022, A, A+4, t);
    saxpy<5>(W3(6), t, S2_11); saxpy<5>(W3(7), t, S2_20); saxpy<5>(W3(8), t, S2_21); }
  // key 3: (1,0,1)  paths 9..12
  { float t[3]; contract<3,1,3>(s_cg+OFF_101, A+1, A, t);
    saxpy<3>(W3(9), t, S1_01); saxpy<3>(W3(10), t, S1_10);
    saxpy<3>(W3(11), t, S1_11); saxpy<3>(W3(12), t, S1_21); }
  // key 4: (1,1,0)  paths 13,14
  { float t[1]; contract<3,3,1>(s_cg+OFF_110, A+1, A+1, t);
    S0_00 = fmaf(W3(13), t[0], S0_00); S0_11 = fmaf(W3(14), t[0], S0_11); }
  // key 5: (1,1,1)  paths 15..18
  { float t[3]; contract<3,3,3>(s_cg+OFF_111, A+1, A+1, t);
    saxpy<3>(W3(15), t, S1_01); saxpy<3>(W3(16), t, S1_10);
    saxpy<3>(W3(17), t, S1_11); saxpy<3>(W3(18), t, S1_21); }
  // key 6: (1,1,2)  paths 19..21
  { float t[5]; contract<3,3,5>(s_cg+OFF_112, A+1, A+1, t);
    saxpy<5>(W3(19), t, S2_11); saxpy<5>(W3(20), t, S2_20); saxpy<5>(W3(21), t, S2_21); }
  // key 7: (1,2,1)  paths 22..25
  { float t[3]; contract<3,5,3>(s_cg+OFF_121, A+1, A+4, t);
    saxpy<3>(W3(22), t, S1_01); saxpy<3>(W3(23), t, S1_10);
    saxpy<3>(W3(24), t, S1_11); saxpy<3>(W3(25), t, S1_21); }
  // key 8: (1,2,2)  paths 26..28
  { float t[5]; contract<3,5,5>(s_cg+OFF_122, A+1, A+4, t);
    saxpy<5>(W3(26), t, S2_11); saxpy<5>(W3(27), t, S2_20); saxpy<5>(W3(28), t, S2_21); }
  // key 9: (1,2,3)  path 29
  { float t[7]; contract<3,5,7>(s_cg+OFF_123, A+1, A+4, t);
    saxpy<7>(W3(29), t, S3_21); }
  // key 10: (2,0,2) paths 30..32
  { float t[5]; contract<5,1,5>(s_cg+OFF_202, A+4, A, t);
    saxpy<5>(W3(30), t, S2_11); saxpy<5>(W3(31), t, S2_20); saxpy<5>(W3(32), t, S2_21); }
  // key 11: (2,1,1) paths 33..36
  { float t[3]; contract<5,3,3>(s_cg+OFF_211, A+4, A+1, t);
    saxpy<3>(W3(33), t, S1_01); saxpy<3>(W3(34), t, S1_10);
    saxpy<3>(W3(35), t, S1_11); saxpy<3>(W3(36), t, S1_21); }
  // key 12: (2,1,2) paths 37..39
  { float t[5]; contract<5,3,5>(s_cg+OFF_212, A+4, A+1, t);
    saxpy<5>(W3(37), t, S2_11); saxpy<5>(W3(38), t, S2_20); saxpy<5>(W3(39), t, S2_21); }
  // key 13: (2,1,3) path 40
  { float t[7]; contract<5,3,7>(s_cg+OFF_213, A+4, A+1, t);
    saxpy<7>(W3(40), t, S3_21); }
  // key 14: (2,2,0) paths 41,42
  { float t[1]; contract<5,5,1>(s_cg+OFF_220, A+4, A+4, t);
    S0_00 = fmaf(W3(41), t[0], S0_00); S0_11 = fmaf(W3(42), t[0], S0_11); }
  // key 15: (2,2,1) paths 43..46
  { float t[3]; contract<5,5,3>(s_cg+OFF_221, A+4, A+4, t);
    saxpy<3>(W3(43), t, S1_01); saxpy<3>(W3(44), t, S1_10);
    saxpy<3>(W3(45), t, S1_11); saxpy<3>(W3(46), t, S1_21); }
  // key 16: (2,2,2) paths 47..49
  { float t[5]; contract<5,5,5>(s_cg+OFF_222, A+4, A+4, t);
    saxpy<5>(W3(47), t, S2_11); saxpy<5>(W3(48), t, S2_20); saxpy<5>(W3(49), t, S2_21); }
  // key 17: (2,2,3) path 50
  { float t[7]; contract<5,5,7>(s_cg+OFF_223, A+4, A+4, t);
    saxpy<7>(W3(50), t, S3_21); }

  // Second stage: contract S with A[l3] using real_cg(l12, l3, lo).
  B0 = fmaf(s_cg[OFF_000], S0_00 * A[0], B0);                  // (0,0,0)
  contract_acc<1,3,3>(s_cg+OFF_011, &S0_11, A+1, B1);          // (0,1,1)
  contract_acc<3,1,3>(s_cg+OFF_101, S1_01,  A,   B1);          // (1,0,1)
  contract_acc<3,3,1>(s_cg+OFF_110, S1_10,  A+1, &B0);         // (1,1,0)
  contract_acc<3,3,3>(s_cg+OFF_111, S1_11,  A+1, B1);          // (1,1,1)
  contract_acc<3,5,3>(s_cg+OFF_121, S1_21,  A+4, B1);          // (1,2,1)
  contract_acc<5,3,3>(s_cg+OFF_211, S2_11,  A+1, B1);          // (2,1,1)
  contract_acc<5,5,1>(s_cg+OFF_220, S2_20,  A+4, &B0);         // (2,2,0)
  contract_acc<5,5,3>(s_cg+OFF_221, S2_21,  A+4, B1);          // (2,2,1)
  contract_acc<7,5,3>(s_cg+OFF_321, S3_21,  A+4, B1);          // (3,2,1)

  g_B[(size_t)n * NCH + c] = make_float4(B0, B1[0], B1[1], B1[2]);
#undef W1
#undef W2
#undef W3
}

// ---------------------------------------------------------------------------
// Phase B: equivariant linear. out[n,f,m] = (1/sqrt(C)) sum_c B[n,c,m] W_m[c,f]
// block = 16 nodes, thread = f (128). W streamed from L2 with 16x node reuse.
// ---------------------------------------------------------------------------
#define NODE_TILE 16
__global__ __launch_bounds__(128)
void phaseB_kernel(const float* __restrict__ lin_w0,
                   const float* __restrict__ lin_w1,
                   float* __restrict__ out) {
  __shared__ float4 sB[NODE_TILE * NCH];   // 32 KB
  const int n0 = blockIdx.x * NODE_TILE;
  const int f  = threadIdx.x;

  const float4* Bp = g_B + (size_t)n0 * NCH;
  for (int i = f; i < NODE_TILE * NCH; i += 128) sB[i] = Bp[i];
  __syncthreads();

  float acc[NODE_TILE][4];
#pragma unroll
  for (int nt = 0; nt < NODE_TILE; nt++)
#pragma unroll
    for (int m = 0; m < 4; m++) acc[nt][m] = 0.f;

  for (int cch = 0; cch < NCH; cch++) {
    float w0 = lin_w0[cch * NFEAT + f];
    float w1v = lin_w1[cch * NFEAT + f];
#pragma unroll
    for (int nt = 0; nt < NODE_TILE; nt++) {
      float4 b = sB[nt * NCH + cch];
      acc[nt][0] = fmaf(b.x, w0,  acc[nt][0]);
      acc[nt][1] = fmaf(b.y, w1v, acc[nt][1]);
      acc[nt][2] = fmaf(b.z, w1v, acc[nt][2]);
      acc[nt][3] = fmaf(b.w, w1v, acc[nt][3]);
    }
  }

  const float s = 0.08838834764831845f;  // 1/sqrt(128)
  float4* op = (float4*)out;
#pragma unroll
  for (int nt = 0; nt < NODE_TILE; nt++) {
    op[(size_t)(n0 + nt) * NFEAT + f] =
      make_float4(acc[nt][0] * s, acc[nt][1] * s, acc[nt][2] * s, acc[nt][3] * s);
  }
}

// ---------------------------------------------------------------------------
// Launch
// ---------------------------------------------------------------------------
extern "C" void kernel_launch(void* const* d_in, const int* in_sizes, int n_in,
                              void* d_out, int out_size) {
  const float* feats   = (const float*)d_in[0];  // [4096,128,9]
  const float* w1      = (const float*)d_in[1];  // [10,2,128]
  const float* w2      = (const float*)d_in[2];  // [10,9,128]
  const float* w3      = (const float*)d_in[3];  // [10,51,128]
  const float* lin_w0  = (const float*)d_in[4];  // [128,128]
  const float* lin_w1  = (const float*)d_in[5];  // [128,128]
  const int*   species = (const int*)d_in[6];    // [4096]

  cg_setup_kernel<<<NTAB, 192>>>();
  phaseA_kernel<<<NNODES, 128>>>(feats, w1, w2, w3, species);
  phaseB_kernel<<<NNODES / NODE_TILE, 128>>>(lin_w0, lin_w1, (float*)d_out);
}

// round 2
// speedup vs baseline: 1.0188x; 1.0188x over previous
#include <cuda_runtime.h>
#include <math.h>

#define NNODES 4096
#define NCH    128
#define NELEM  10
#define NFEAT  128

typedef unsigned long long u64;

// ---------------------------------------------------------------------------
// f32x2 packed-math helpers (Blackwell FFMA2 — only reachable via PTX)
// ---------------------------------------------------------------------------
__device__ __forceinline__ u64 f2pack(float lo, float hi) {
  u64 r; asm("mov.b64 %0,{%1,%2};" : "=l"(r) : "f"(lo), "f"(hi)); return r;
}
__device__ __forceinline__ void f2unpack(u64 v, float& lo, float& hi) {
  asm("mov.b64 {%0,%1},%2;" : "=f"(lo), "=f"(hi) : "l"(v));
}
__device__ __forceinline__ u64 f2fma(u64 a, u64 b, u64 c) {
  u64 d; asm("fma.rn.f32x2 %0,%1,%2,%3;" : "=l"(d) : "l"(a), "l"(b), "l"(c)); return d;
}
__device__ __forceinline__ u64 f2mul(u64 a, u64 b) {
  u64 d; asm("mul.rn.f32x2 %0,%1,%2;" : "=l"(d) : "l"(a), "l"(b)); return d;
}

// ---------------------------------------------------------------------------
// CG table registry: 19 unique (l1,l2,l3) real-CG tensors, packed into g_cg2
// (each coefficient stored DUPLICATED as a f32x2 pair for broadcast FFMA2).
// ---------------------------------------------------------------------------
#define NTAB 19
__constant__ int c_tab_l[NTAB][3] = {
  {0,0,0},{0,1,1},{1,0,1},{1,1,0},{1,1,1},{1,2,1},{2,1,1},{2,2,0},{2,2,1},
  {0,2,2},{1,1,2},{1,2,2},{1,2,3},{2,0,2},{2,1,2},{2,1,3},{2,2,2},{2,2,3},{3,2,1}};
__constant__ int c_tab_off[NTAB] = {0,1,10,19,28,55,100,145,170,245,270,315,390,495,520,595,700,825,1000};
#define CG_TOTAL 1105

#define OFF_000 0
#define OFF_011 1
#define OFF_101 10
#define OFF_110 19
#define OFF_111 28
#define OFF_121 55
#define OFF_211 100
#define OFF_220 145
#define OFF_221 170
#define OFF_022 245
#define OFF_112 270
#define OFF_122 315
#define OFF_123 390
#define OFF_202 495
#define OFF_212 520
#define OFF_213 595
#define OFF_222 700
#define OFF_223 825
#define OFF_321 1000

__device__ u64    g_cg2[CG_TOTAL];     // duplicated-lane CG coefficients
__device__ float4 g_B[NNODES * NCH];   // per (node,channel): {B0, B1x, B1y, B1z}

__constant__ float c_fact[11] = {1.f,1.f,2.f,6.f,24.f,120.f,720.f,5040.f,
                                 40320.f,362880.f,3628800.f};

// ---------------------------------------------------------------------------
// Setup: real CG coefficients (e3nn convention), fp32, on device.
// Two-phase: su2cg(m1,m2) computed once per table into smem, then reused.
// ---------------------------------------------------------------------------
__device__ float su2cg(int j1,int m1,int j2,int m2,int j3,int m3) {
  if (m1 + m2 != m3) return 0.f;
  int vmin = max(max(-j1 + j2 + m3, -j1 + m1), 0);
  int vmax = min(min(j2 + j3 + m1, j3 - j1 + j2), j3 + m3);
  if (vmax < vmin) return 0.f;
  float C = sqrtf((2.f*j3 + 1.f) * c_fact[j3+j1-j2] * c_fact[j3-j1+j2] * c_fact[j1+j2-j3]
                  * c_fact[j3+m3] * c_fact[j3-m3]
                  / (c_fact[j1+j2+j3+1] * c_fact[j1-m1] * c_fact[j1+m1]
                     * c_fact[j2-m2] * c_fact[j2+m2]));
  float S = 0.f;
  for (int v = vmin; v <= vmax; v++) {
    float t = c_fact[j2+j3+m1-v] * c_fact[j1-m1+v]
            / (c_fact[v] * c_fact[j3-j1+j2-v] * c_fact[j3+m3-v] * c_fact[v+j1-j2-m3]);
    S += ((v + j2 + m2) & 1) ? -t : t;
  }
  return C * S;
}

// c2r(l)[r][c], complex, including the (-i)^l global phase.
__device__ float2 c2r_e(int l, int r, int c) {
  int m = r - l;
  const float IS2 = 0.7071067811865476f;
  float re = 0.f, im = 0.f;
  if (m < 0) {
    if (c == l - m)      re = IS2;
    else if (c == l + m) im = -IS2;
  } else if (m == 0) {
    if (c == l) re = 1.f;
  } else {
    float s = (m & 1) ? -1.f : 1.f;
    if (c == l + m)      re = s * IS2;
    else if (c == l - m) im = s * IS2;
  }
  float tr;
  switch (l & 3) {
    case 1: tr = re; re = im;  im = -tr; break;
    case 2: re = -re; im = -im;          break;
    case 3: tr = re; re = -im; im = tr;  break;
    default: break;
  }
  return make_float2(re, im);
}

__global__ void cg_setup_kernel() {
  __shared__ float s_su2[35];
  int t  = blockIdx.x;
  int l1 = c_tab_l[t][0], l2 = c_tab_l[t][1], l3 = c_tab_l[t][2];
  int d1 = 2*l1+1, d2 = 2*l2+1, d3 = 2*l3+1;

  if (threadIdx.x < d1 * d2) {
    int i = threadIdx.x / d2, k = threadIdx.x % d2;
    int m1 = i - l1, m2 = k - l2, m3 = m1 + m2;
    s_su2[threadIdx.x] = (m3 >= -l3 && m3 <= l3) ? su2cg(l1, m1, l2, m2, l3, m3) : 0.f;
  }
  __syncthreads();

  int nent = d1 * d2 * d3;
  u64* out = g_cg2 + c_tab_off[t];
  for (int e = threadIdx.x; e < nent; e += blockDim.x) {
    int m    = e % d3;
    int jl   = e / d3;
    int lcol = jl % d2;
    int j    = jl / d2;
    float acc = 0.f;
    for (int i = 0; i < d1; i++)
      for (int k = 0; k < d2; k++) {
        int m1 = i - l1, m2 = k - l2, m3 = m1 + m2;
        if (m3 < -l3 || m3 > l3) continue;
        float cc = s_su2[i * d2 + k];
        if (cc == 0.f) continue;
        float2 q1 = c2r_e(l1, i, j);
        float2 q2 = c2r_e(l2, k, lcol);
        float2 q3 = c2r_e(l3, m3 + l3, m);
        float pr = q1.x*q2.x - q1.y*q2.y;
        float pi = q1.x*q2.y + q1.y*q2.x;
        acc += cc * (pr * q3.x + pi * q3.y);
      }
    out[e] = f2pack(acc, acc);
  }
}

// ---------------------------------------------------------------------------
// Packed contraction helpers (compile-time dims, fully unrolled)
// ---------------------------------------------------------------------------
template<int D1,int D2,int D3>
__device__ __forceinline__ void contract2(const u64* __restrict__ cg,
                                          const u64* a, const u64* b, u64* t) {
#pragma unroll
  for (int k = 0; k < D3; k++) t[k] = 0ULL;
#pragma unroll
  for (int i = 0; i < D1; i++)
#pragma unroll
    for (int j = 0; j < D2; j++) {
      u64 p = f2mul(a[i], b[j]);
#pragma unroll
      for (int k = 0; k < D3; k++) t[k] = f2fma(cg[(i*D2+j)*D3+k], p, t[k]);
    }
}

template<int D1,int D2,int D3>
__device__ __forceinline__ void contract_acc2(const u64* __restrict__ cg,
                                              const u64* a, const u64* b, u64* B) {
#pragma unroll
  for (int i = 0; i < D1; i++)
#pragma unroll
    for (int j = 0; j < D2; j++) {
      u64 p = f2mul(a[i], b[j]);
#pragma unroll
      for (int k = 0; k < D3; k++) B[k] = f2fma(cg[(i*D2+j)*D3+k], p, B[k]);
    }
}

template<int D>
__device__ __forceinline__ void saxpy2(u64 w, const u64* t, u64* S) {
#pragma unroll
  for (int k = 0; k < D; k++) S[k] = f2fma(w, t[k], S[k]);
}

// ---------------------------------------------------------------------------
// Phase A: two nodes per thread-lane-pair (f32x2). block = node pair,
// thread = channel. Each unique first-stage contraction computed ONCE and
// fed to both the order-2 (w2) and order-3 (w3) accumulators.
// ---------------------------------------------------------------------------
__global__ __launch_bounds__(128)
void phaseA_kernel(const float* __restrict__ feats,
                   const float* __restrict__ w1,
                   const float* __restrict__ w2,
                   const float* __restrict__ w3,
                   const int*   __restrict__ species) {
  __shared__ u64 s_cg[CG_TOTAL];

  const int c  = threadIdx.x;
  const int n0 = blockIdx.x * 2;
  const int n1 = n0 + 1;

  for (int i = c; i < CG_TOTAL; i += 128) s_cg[i] = g_cg2[i];
  __syncthreads();

  const int e0 = species[n0];
  const int e1 = species[n1];

  const float* f0 = feats + ((size_t)n0 * NCH + c) * 9;
  const float* f1 = feats + ((size_t)n1 * NCH + c) * 9;
  u64 A[9];
#pragma unroll
  for (int k = 0; k < 9; k++) A[k] = f2pack(f0[k], f1[k]);

  const float* w1a = w1 + (size_t)(e0 * 2)  * NCH + c;
  const float* w1b = w1 + (size_t)(e1 * 2)  * NCH + c;
  const float* w2a = w2 + (size_t)(e0 * 9)  * NCH + c;
  const float* w2b = w2 + (size_t)(e1 * 9)  * NCH + c;
  const float* w3a = w3 + (size_t)(e0 * 51) * NCH + c;
  const float* w3b = w3 + (size_t)(e1 * 51) * NCH + c;
#define W1(p) f2pack(w1a[(p)*NCH], w1b[(p)*NCH])
#define W2(p) f2pack(w2a[(p)*NCH], w2b[(p)*NCH])
#define W3(p) f2pack(w3a[(p)*NCH], w3b[(p)*NCH])

  u64 B0 = 0ULL;
  u64 B1[3] = {0ULL, 0ULL, 0ULL};

  // ---- correlation order 1 ----
  B0 = f2fma(W1(0), A[0], B0);
  {
    u64 w = W1(1);
#pragma unroll
    for (int k = 0; k < 3; k++) B1[k] = f2fma(w, A[1 + k], B1[k]);
  }

  // ---- unified first-stage contractions (order-2 + order-3 stage 1) ----
  u64 S0_00 = 0ULL, S0_11 = 0ULL;
  u64 S1_01[3] = {0,0,0}, S1_10[3] = {0,0,0};
  u64 S1_11[3] = {0,0,0}, S1_21[3] = {0,0,0};
  u64 S2_11[5] = {0,0,0,0,0}, S2_20[5] = {0,0,0,0,0}, S2_21[5] = {0,0,0,0,0};
  u64 S3_21[7] = {0,0,0,0,0,0,0};

  // key (0,0,0): order2 p0; order3 p0,p1
  { u64 t[1]; contract2<1,1,1>(s_cg+OFF_000, A, A, t);
    B0 = f2fma(W2(0), t[0], B0);
    S0_00 = f2fma(W3(0), t[0], S0_00); S0_11 = f2fma(W3(1), t[0], S0_11); }
  // key (0,1,1): order2 p1; order3 p2..5
  { u64 t[3]; contract2<1,3,3>(s_cg+OFF_011, A, A+1, t);
    saxpy2<3>(W2(1), t, B1);
    saxpy2<3>(W3(2), t, S1_01); saxpy2<3>(W3(3), t, S1_10);
    saxpy2<3>(W3(4), t, S1_11); saxpy2<3>(W3(5), t, S1_21); }
  // key (0,2,2): order3 p6..8
  { u64 t[5]; contract2<1,5,5>(s_cg+OFF_022, A, A+4, t);
    saxpy2<5>(W3(6), t, S2_11); saxpy2<5>(W3(7), t, S2_20); saxpy2<5>(W3(8), t, S2_21); }
  // key (1,0,1): order2 p2; order3 p9..12
  { u64 t[3]; contract2<3,1,3>(s_cg+OFF_101, A+1, A, t);
    saxpy2<3>(W2(2), t, B1);
    saxpy2<3>(W3(9), t, S1_01); saxpy2<3>(W3(10), t, S1_10);
    saxpy2<3>(W3(11), t, S1_11); saxpy2<3>(W3(12), t, S1_21); }
  // key (1,1,0): order2 p3; order3 p13,14
  { u64 t[1]; contract2<3,3,1>(s_cg+OFF_110, A+1, A+1, t);
    B0 = f2fma(W2(3), t[0], B0);
    S0_00 = f2fma(W3(13), t[0], S0_00); S0_11 = f2fma(W3(14), t[0], S0_11); }
  // key (1,1,1): order2 p4; order3 p15..18
  { u64 t[3]; contract2<3,3,3>(s_cg+OFF_111, A+1, A+1, t);
    saxpy2<3>(W2(4), t, B1);
    saxpy2<3>(W3(15), t, S1_01); saxpy2<3>(W3(16), t, S1_10);
    saxpy2<3>(W3(17), t, S1_11); saxpy2<3>(W3(18), t, S1_21); }
  // key (1,1,2): order3 p19..21
  { u64 t[5]; contract2<3,3,5>(s_cg+OFF_112, A+1, A+1, t);
    saxpy2<5>(W3(19), t, S2_11); saxpy2<5>(W3(20), t, S2_20); saxpy2<5>(W3(21), t, S2_21); }
  // key (1,2,1): order2 p5; order3 p22..25
  { u64 t[3]; contract2<3,5,3>(s_cg+OFF_121, A+1, A+4, t);
    saxpy2<3>(W2(5), t, B1);
    saxpy2<3>(W3(22), t, S1_01); saxpy2<3>(W3(23), t, S1_10);
    saxpy2<3>(W3(24), t, S1_11); saxpy2<3>(W3(25), t, S1_21); }
  // key (1,2,2): order3 p26..28
  { u64 t[5]; contract2<3,5,5>(s_cg+OFF_122, A+1, A+4, t);
    saxpy2<5>(W3(26), t, S2_11); saxpy2<5>(W3(27), t, S2_20); saxpy2<5>(W3(28), t, S2_21); }
  // key (1,2,3): order3 p29
  { u64 t[7]; contract2<3,5,7>(s_cg+OFF_123, A+1, A+4, t);
    saxpy2<7>(W3(29), t, S3_21); }
  // key (2,0,2): order3 p30..32
  { u64 t[5]; contract2<5,1,5>(s_cg+OFF_202, A+4, A, t);
    saxpy2<5>(W3(30), t, S2_11); saxpy2<5>(W3(31), t, S2_20); saxpy2<5>(W3(32), t, S2_21); }
  // key (2,1,1): order2 p6; order3 p33..36
  { u64 t[3]; contract2<5,3,3>(s_cg+OFF_211, A+4, A+1, t);
    saxpy2<3>(W2(6), t, B1);
    saxpy2<3>(W3(33), t, S1_01); saxpy2<3>(W3(34), t, S1_10);
    saxpy2<3>(W3(35), t, S1_11); saxpy2<3>(W3(36), t, S1_21); }
  // key (2,1,2): order3 p37..39
  { u64 t[5]; contract2<5,3,5>(s_cg+OFF_212, A+4, A+1, t);
    saxpy2<5>(W3(37), t, S2_11); saxpy2<5>(W3(38), t, S2_20); saxpy2<5>(W3(39), t, S2_21); }
  // key (2,1,3): order3 p40
  { u64 t[7]; contract2<5,3,7>(s_cg+OFF_213, A+4, A+1, t);
    saxpy2<7>(W3(40), t, S3_21); }
  // key (2,2,0): order2 p7; order3 p41,42
  { u64 t[1]; contract2<5,5,1>(s_cg+OFF_220, A+4, A+4, t);
    B0 = f2fma(W2(7), t[0], B0);
    S0_00 = f2fma(W3(41), t[0], S0_00); S0_11 = f2fma(W3(42), t[0], S0_11); }
  // key (2,2,1): order2 p8; order3 p43..46
  { u64 t[3]; contract2<5,5,3>(s_cg+OFF_221, A+4, A+4, t);
    saxpy2<3>(W2(8), t, B1);
    saxpy2<3>(W3(43), t, S1_01); saxpy2<3>(W3(44), t, S1_10);
    saxpy2<3>(W3(45), t, S1_11); saxpy2<3>(W3(46), t, S1_21); }
  // key (2,2,2): order3 p47..49
  { u64 t[5]; contract2<5,5,5>(s_cg+OFF_222, A+4, A+4, t);
    saxpy2<5>(W3(47), t, S2_11); saxpy2<5>(W3(48), t, S2_20); saxpy2<5>(W3(49), t, S2_21); }
  // key (2,2,3): order3 p50
  { u64 t[7]; contract2<5,5,7>(s_cg+OFF_223, A+4, A+4, t);
    saxpy2<7>(W3(50), t, S3_21); }

  // ---- order-3 second stage: contract S with A[l3] via real_cg(l12,l3,lo) ----
  B0 = f2fma(s_cg[OFF_000], f2mul(S0_00, A[0]), B0);           // (0,0,0)
  contract_acc2<1,3,3>(s_cg+OFF_011, &S0_11, A+1, B1);         // (0,1,1)
  contract_acc2<3,1,3>(s_cg+OFF_101, S1_01,  A,   B1);         // (1,0,1)
  contract_acc2<3,3,1>(s_cg+OFF_110, S1_10,  A+1, &B0);        // (1,1,0)
  contract_acc2<3,3,3>(s_cg+OFF_111, S1_11,  A+1, B1);         // (1,1,1)
  contract_acc2<3,5,3>(s_cg+OFF_121, S1_21,  A+4, B1);         // (1,2,1)
  contract_acc2<5,3,3>(s_cg+OFF_211, S2_11,  A+1, B1);         // (2,1,1)
  contract_acc2<5,5,1>(s_cg+OFF_220, S2_20,  A+4, &B0);        // (2,2,0)
  contract_acc2<5,5,3>(s_cg+OFF_221, S2_21,  A+4, B1);         // (2,2,1)
  contract_acc2<7,5,3>(s_cg+OFF_321, S3_21,  A+4, B1);         // (3,2,1)

  float b0l, b0h, xl, xh, yl, yh, zl, zh;
  f2unpack(B0, b0l, b0h);
  f2unpack(B1[0], xl, xh);
  f2unpack(B1[1], yl, yh);
  f2unpack(B1[2], zl, zh);
  g_B[(size_t)n0 * NCH + c] = make_float4(b0l, xl, yl, zl);
  g_B[(size_t)n1 * NCH + c] = make_float4(b0h, xh, yh, zh);
#undef W1
#undef W2
#undef W3
}

// ---------------------------------------------------------------------------
// Phase B: equivariant linear, f32x2 over node pairs.
// block = 16 nodes (8 pairs), thread = feature f.
// ---------------------------------------------------------------------------
#define NODE_TILE 16
__global__ __launch_bounds__(128)
void phaseB_kernel(const float* __restrict__ lin_w0,
                   const float* __restrict__ lin_w1,
                   float* __restrict__ out) {
  __shared__ ulonglong2 s_b[8 * NCH * 2];   // (pair,cch) -> {m0,m1},{m2,m3} packed pairs
  const int n0 = blockIdx.x * NODE_TILE;
  const int f  = threadIdx.x;

  for (int t = f; t < 8 * NCH; t += 128) {
    int p = t >> 7, cch = t & 127;
    float4 a = g_B[(size_t)(n0 + 2*p)     * NCH + cch];
    float4 b = g_B[(size_t)(n0 + 2*p + 1) * NCH + cch];
    ulonglong2 u0, u1;
    u0.x = f2pack(a.x, b.x); u0.y = f2pack(a.y, b.y);
    u1.x = f2pack(a.z, b.z); u1.y = f2pack(a.w, b.w);
    s_b[t * 2]     = u0;
    s_b[t * 2 + 1] = u1;
  }
  __syncthreads();

  u64 acc[8][4];
#pragma unroll
  for (int p = 0; p < 8; p++)
#pragma unroll
    for (int m = 0; m < 4; m++) acc[p][m] = 0ULL;

  for (int cch = 0; cch < NCH; cch++) {
    float w0  = lin_w0[cch * NFEAT + f];
    float w1v = lin_w1[cch * NFEAT + f];
    u64 W0 = f2pack(w0, w0);
    u64 Wv = f2pack(w1v, w1v);
#pragma unroll
    for (int p = 0; p < 8; p++) {
      ulonglong2 u0 = s_b[(p * NCH + cch) * 2];
      ulonglong2 u1 = s_b[(p * NCH + cch) * 2 + 1];
      acc[p][0] = f2fma(u0.x, W0, acc[p][0]);
      acc[p][1] = f2fma(u0.y, Wv, acc[p][1]);
      acc[p][2] = f2fma(u1.x, Wv, acc[p][2]);
      acc[p][3] = f2fma(u1.y, Wv, acc[p][3]);
    }
  }

  const float s = 0.08838834764831845f;  // 1/sqrt(128)
  float4* op = (float4*)out;
#pragma unroll
  for (int p = 0; p < 8; p++) {
    float m0l,m0h,m1l,m1h,m2l,m2h,m3l,m3h;
    f2unpack(acc[p][0], m0l, m0h);
    f2unpack(acc[p][1], m1l, m1h);
    f2unpack(acc[p][2], m2l, m2h);
    f2unpack(acc[p][3], m3l, m3h);
    op[(size_t)(n0 + 2*p)     * NFEAT + f] = make_float4(m0l*s, m1l*s, m2l*s, m3l*s);
    op[(size_t)(n0 + 2*p + 1) * NFEAT + f] = make_float4(m0h*s, m1h*s, m2h*s, m3h*s);
  }
}

// ---------------------------------------------------------------------------
// Launch
// ---------------------------------------------------------------------------
extern "C" void kernel_launch(void* const* d_in, const int* in_sizes, int n_in,
                              void* d_out, int out_size) {
  const float* feats   = (const float*)d_in[0];  // [4096,128,9]
  const float* w1      = (const float*)d_in[1];  // [10,2,128]
  const float* w2      = (const float*)d_in[2];  // [10,9,128]
  const float* w3      = (const float*)d_in[3];  // [10,51,128]
  const float* lin_w0  = (const float*)d_in[4];  // [128,128]
  const float* lin_w1  = (const float*)d_in[5];  // [128,128]
  const int*   species = (const int*)d_in[6];    // [4096]

  cg_setup_kernel<<<NTAB, 192>>>();
  phaseA_kernel<<<NNODES / 2, 128>>>(feats, w1, w2, w3, species);
  phaseB_kernel<<<NNODES / NODE_TILE, 128>>>(lin_w0, lin_w1, (float*)d_out);
}

// round 3
// speedup vs baseline: 2.0365x; 1.9988x over previous
#include <cuda_runtime.h>
#include <math.h>

#define NNODES 4096
#define NCH    128
#define NELEM  10
#define NFEAT  128

// ---------------------------------------------------------------------------
// Padded CG storage: rows of 8 floats. Row = (i*D2+j) within each table
// (or symmetric-pair index for sym-packed tables). Layout (row offsets):
//   T112p (sym,6) @0 | T121 (15) @6 | T122 (15) @21 | T123 (15) @36
//   T221 (25) @51 | T222p (sym,15) @76 | T321 (35) @91 | CONSTS @126
// CONSTS row: {c110, c220, c111, 0...}  (cg(l,l,0)=c·δ ; cg(1,1,1)=c·ε)
// ---------------------------------------------------------------------------
#define R112 0
#define R121 6
#define R122 21
#define R123 36
#define R221 51
#define R222 76
#define R321 91
#define RCON 126
#define NROWS 127

__device__ float  g_cgp[NROWS * 8];
__device__ float4 g_B[NNODES * NCH];   // per (node,channel): {B0, B1x, B1y, B1z}

__constant__ float c_fact[11] = {1.f,1.f,2.f,6.f,24.f,120.f,720.f,5040.f,
                                 40320.f,362880.f,3628800.f};
// table spec: l1,l2,l3,row_off,sym
__constant__ int c_spec[7][5] = {
  {1,1,2, R112, 1},
  {1,2,1, R121, 0},
  {1,2,2, R122, 0},
  {1,2,3, R123, 0},
  {2,2,1, R221, 0},
  {2,2,2, R222, 1},
  {3,2,1, R321, 0}};
__constant__ int P6i[6]  = {0,0,0,1,1,2};
__constant__ int P6j[6]  = {0,1,2,1,2,2};
__constant__ int P15i[15]= {0,0,0,0,0,1,1,1,1,2,2,2,3,3,4};
__constant__ int P15j[15]= {0,1,2,3,4,1,2,3,4,2,3,4,3,4,4};

// ---------------------------------------------------------------------------
// su2 CG + real change-of-basis (mirrors reference exactly, fp32)
// ---------------------------------------------------------------------------
__device__ float su2cg(int j1,int m1,int j2,int m2,int j3,int m3) {
  if (m1 + m2 != m3) return 0.f;
  int vmin = max(max(-j1 + j2 + m3, -j1 + m1), 0);
  int vmax = min(min(j2 + j3 + m1, j3 - j1 + j2), j3 + m3);
  if (vmax < vmin) return 0.f;
  float C = sqrtf((2.f*j3 + 1.f) * c_fact[j3+j1-j2] * c_fact[j3-j1+j2] * c_fact[j1+j2-j3]
                  * c_fact[j3+m3] * c_fact[j3-m3]
                  / (c_fact[j1+j2+j3+1] * c_fact[j1-m1] * c_fact[j1+m1]
                     * c_fact[j2-m2] * c_fact[j2+m2]));
  float S = 0.f;
  for (int v = vmin; v <= vmax; v++) {
    float t = c_fact[j2+j3+m1-v] * c_fact[j1-m1+v]
            / (c_fact[v] * c_fact[j3-j1+j2-v] * c_fact[j3+m3-v] * c_fact[v+j1-j2-m3]);
    S += ((v + j2 + m2) & 1) ? -t : t;
  }
  return C * S;
}

__device__ float2 c2r_e(int l, int r, int c) {
  int m = r - l;
  const float IS2 = 0.7071067811865476f;
  float re = 0.f, im = 0.f;
  if (m < 0) {
    if (c == l - m)      re = IS2;
    else if (c == l + m) im = -IS2;
  } else if (m == 0) {
    if (c == l) re = 1.f;
  } else {
    float s = (m & 1) ? -1.f : 1.f;
    if (c == l + m)      re = s * IS2;
    else if (c == l - m) im = s * IS2;
  }
  float tr;
  switch (l & 3) {
    case 1: tr = re; re = im;  im = -tr; break;
    case 2: re = -re; im = -im;          break;
    case 3: tr = re; re = -im; im = tr;  break;
    default: break;
  }
  return make_float2(re, im);
}

// one real-CG entry, standalone (for the 3 structure constants)
__device__ float cg_entry(int l1,int l2,int l3,int i,int j,int k) {
  int d1 = 2*l1+1, d2 = 2*l2+1;
  float acc = 0.f;
  for (int i2 = 0; i2 < d1; i2++)
    for (int k2 = 0; k2 < d2; k2++) {
      int m1 = i2 - l1, m2 = k2 - l2, m3 = m1 + m2;
      if (m3 < -l3 || m3 > l3) continue;
      float cc = su2cg(l1, m1, l2, m2, l3, m3);
      if (cc == 0.f) continue;
      float2 q1 = c2r_e(l1, i2, i);
      float2 q2 = c2r_e(l2, k2, j);
      float2 q3 = c2r_e(l3, m3 + l3, k);
      float pr = q1.x*q2.x - q1.y*q2.y;
      float pi = q1.x*q2.y + q1.y*q2.x;
      acc += cc * (pr * q3.x + pi * q3.y);
    }
  return acc;
}

__global__ void cg_setup_kernel() {
  int b = blockIdx.x;
  int tid = threadIdx.x;
  if (b == 7) {
    // structure constants row
    if (tid == 0) g_cgp[RCON*8 + 0] = cg_entry(1,1,0, 0,0,0);   // c110
    if (tid == 1) g_cgp[RCON*8 + 1] = cg_entry(2,2,0, 0,0,0);   // c220
    if (tid == 2) g_cgp[RCON*8 + 2] = cg_entry(1,1,1, 0,1,2);   // c111 (eps coeff)
    if (tid >= 3 && tid < 8) g_cgp[RCON*8 + tid] = 0.f;
    return;
  }
  __shared__ float s_su2[35];
  int l1 = c_spec[b][0], l2 = c_spec[b][1], l3 = c_spec[b][2];
  int off = c_spec[b][3], sym = c_spec[b][4];
  int d1 = 2*l1+1, d2 = 2*l2+1, d3 = 2*l3+1;

  if (tid < d1 * d2) {
    int i2 = tid / d2, k2 = tid % d2;
    int m1 = i2 - l1, m2 = k2 - l2, m3 = m1 + m2;
    s_su2[tid] = (m3 >= -l3 && m3 <= l3) ? su2cg(l1, m1, l2, m2, l3, m3) : 0.f;
  }
  __syncthreads();

  int nrows = sym ? d1*(d1+1)/2 : d1*d2;
  for (int e = tid; e < nrows * 8; e += blockDim.x) {
    int r = e >> 3, k = e & 7;
    float v = 0.f;
    if (k < d3) {
      int i, j;
      if (sym) {
        if (d1 == 3) { i = P6i[r];  j = P6j[r];  }
        else         { i = P15i[r]; j = P15j[r]; }
      } else { i = r / d2; j = r % d2; }
      float acc = 0.f;
      for (int i2 = 0; i2 < d1; i2++)
        for (int k2 = 0; k2 < d2; k2++) {
          int m1 = i2 - l1, m2 = k2 - l2, m3 = m1 + m2;
          if (m3 < -l3 || m3 > l3) continue;
          float cc = s_su2[i2 * d2 + k2];
          if (cc == 0.f) continue;
          float2 q1 = c2r_e(l1, i2, i);
          float2 q2 = c2r_e(l2, k2, j);
          float2 q3 = c2r_e(l3, m3 + l3, k);
          float pr = q1.x*q2.x - q1.y*q2.y;
          float pi = q1.x*q2.y + q1.y*q2.x;
          acc += cc * (pr * q3.x + pi * q3.y);
        }
      if (sym && i != j) acc *= 2.f;   // fold (i,j)+(j,i) for symmetric input
      v = acc;
    }
    g_cgp[(off + r) * 8 + k] = v;
  }
}

// ---------------------------------------------------------------------------
// contraction helpers on padded rows (accumulating)
// ---------------------------------------------------------------------------
template<int D1,int D2>
__device__ __forceinline__ void c3acc(const float4* __restrict__ s, const int base,
                                      const float* a, const float* b, float* t) {
#pragma unroll
  for (int i = 0; i < D1; i++)
#pragma unroll
    for (int j = 0; j < D2; j++) {
      float p = a[i] * b[j];
      float4 r = s[2*(base + i*D2 + j)];
      t[0] = fmaf(r.x, p, t[0]); t[1] = fmaf(r.y, p, t[1]); t[2] = fmaf(r.z, p, t[2]);
    }
}
// transposed (first table index runs over `a` length D1=5, table rows j*5+i)
__device__ __forceinline__ void c3accT53(const float4* __restrict__ s, const int base,
                                         const float* a, const float* b, float* t) {
#pragma unroll
  for (int j = 0; j < 3; j++)
#pragma unroll
    for (int i = 0; i < 5; i++) {
      float p = a[i] * b[j];
      float4 r = s[2*(base + j*5 + i)];
      t[0] = fmaf(r.x, p, t[0]); t[1] = fmaf(r.y, p, t[1]); t[2] = fmaf(r.z, p, t[2]);
    }
}
template<int D1,int D2>
__device__ __forceinline__ void c5acc(const float4* __restrict__ s, const int base,
                                      const float* a, const float* b, float* t) {
#pragma unroll
  for (int i = 0; i < D1; i++)
#pragma unroll
    for (int j = 0; j < D2; j++) {
      float p = a[i] * b[j];
      int row = base + i*D2 + j;
      float4 r0 = s[2*row], r1 = s[2*row+1];
      t[0] = fmaf(r0.x, p, t[0]); t[1] = fmaf(r0.y, p, t[1]);
      t[2] = fmaf(r0.z, p, t[2]); t[3] = fmaf(r0.w, p, t[3]);
      t[4] = fmaf(r1.x, p, t[4]);
    }
}
template<int D1,int D2>
__device__ __forceinline__ void c7acc(const float4* __restrict__ s, const int base,
                                      const float* a, const float* b, float* t) {
#pragma unroll
  for (int i = 0; i < D1; i++)
#pragma unroll
    for (int j = 0; j < D2; j++) {
      float p = a[i] * b[j];
      int row = base + i*D2 + j;
      float4 r0 = s[2*row], r1 = s[2*row+1];
      t[0] = fmaf(r0.x, p, t[0]); t[1] = fmaf(r0.y, p, t[1]);
      t[2] = fmaf(r0.z, p, t[2]); t[3] = fmaf(r0.w, p, t[3]);
      t[4] = fmaf(r1.x, p, t[4]); t[5] = fmaf(r1.y, p, t[5]);
      t[6] = fmaf(r1.z, p, t[6]);
    }
}
// sym-packed 5-out contraction over precomputed pair products
template<int NP>
__device__ __forceinline__ void c5sym(const float4* __restrict__ s, const int base,
                                      const float* pp, float* t) {
#pragma unroll
  for (int r = 0; r < NP; r++) {
    float p = pp[r];
    float4 r0 = s[2*(base + r)], r1 = s[2*(base + r) + 1];
    t[0] = fmaf(r0.x, p, t[0]); t[1] = fmaf(r0.y, p, t[1]);
    t[2] = fmaf(r0.z, p, t[2]); t[3] = fmaf(r0.w, p, t[3]);
    t[4] = fmaf(r1.x, p, t[4]);
  }
}

// ---------------------------------------------------------------------------
// Phase A: per (node,channel) product basis using symmetry-reduced paths.
// ---------------------------------------------------------------------------
__global__ __launch_bounds__(128)
void phaseA_kernel(const float* __restrict__ feats,
                   const float* __restrict__ w1,
                   const float* __restrict__ w2,
                   const float* __restrict__ w3,
                   const int*   __restrict__ species) {
  __shared__ float4 s_cg[NROWS * 2];

  const int c = threadIdx.x;
  const int n = blockIdx.x;

  const float4* gsrc = (const float4*)g_cgp;
  for (int i = c; i < NROWS * 2; i += 128) s_cg[i] = gsrc[i];
  __syncthreads();

  const int e = species[n];
  const float* fp = feats + ((size_t)n * NCH + c) * 9;
  float A[9];
#pragma unroll
  for (int k = 0; k < 9; k++) A[k] = fp[k];
  const float  A0 = A[0];
  const float* A1 = A + 1;
  const float* A2 = A + 4;

  const float* w1p = w1 + (size_t)(e * 2)  * NCH + c;
  const float* w2p = w2 + (size_t)(e * 9)  * NCH + c;
  const float* w3p = w3 + (size_t)(e * 51) * NCH + c;
#define W1(p) w1p[(p)*NCH]
#define W2(p) w2p[(p)*NCH]
#define W3(p) w3p[(p)*NCH]

  const float4 cr  = s_cg[2*RCON];
  const float c110 = cr.x, c220 = cr.y, c111 = cr.z;

  // ---- order 1 ----
  float B0 = W1(0) * A0;
  float B1[3];
#pragma unroll
  for (int k = 0; k < 3; k++) B1[k] = W1(1) * A1[k];

  // ---- stage-1 scalars ----
  float t000 = A0 * A0;
  B0 = fmaf(W2(0), t000, B0);
  float S0_00 = W3(0) * t000;
  float S0_11 = W3(1) * t000;

  float d11 = fmaf(A1[2], A1[2], fmaf(A1[1], A1[1], A1[0]*A1[0]));
  float d22 = fmaf(A2[4], A2[4], fmaf(A2[3], A2[3],
               fmaf(A2[2], A2[2], fmaf(A2[1], A2[1], A2[0]*A2[0]))));
  float t110 = c110 * d11;               // cg(1,1,0) = c·δ
  B0    = fmaf(W2(3),  t110, B0);
  S0_00 = fmaf(W3(13), t110, S0_00);
  S0_11 = fmaf(W3(14), t110, S0_11);
  float t220 = c220 * d22;               // cg(2,2,0) = c·δ
  B0    = fmaf(W2(7),  t220, B0);
  S0_00 = fmaf(W3(41), t220, S0_00);
  S0_11 = fmaf(W3(42), t220, S0_11);

  // ---- t011 = A0*A1 (== t101) : δ couplings ----
  float S1_01[3], S1_10[3], S1_11[3], S1_21[3];
  {
    float u = (W2(1) + W2(2)) * A0;
#pragma unroll
    for (int k = 0; k < 3; k++) B1[k] = fmaf(u, A1[k], B1[k]);
    float u01 = (W3(2) + W3(9))  * A0;
    float u10 = (W3(3) + W3(10)) * A0;
    float u11 = (W3(4) + W3(11)) * A0;
    float u21 = (W3(5) + W3(12)) * A0;
#pragma unroll
    for (int k = 0; k < 3; k++) {
      S1_01[k] = u01 * A1[k];
      S1_10[k] = u10 * A1[k];
      S1_11[k] = u11 * A1[k];
      S1_21[k] = u21 * A1[k];
    }
  }
  // ---- t022 = A0*A2 (== t202) ----
  float S2_11[5], S2_20[5], S2_21[5];
  {
    float u11 = (W3(6) + W3(30)) * A0;
    float u20 = (W3(7) + W3(31)) * A0;
    float u21 = (W3(8) + W3(32)) * A0;
#pragma unroll
    for (int k = 0; k < 5; k++) {
      S2_11[k] = u11 * A2[k];
      S2_20[k] = u20 * A2[k];
      S2_21[k] = u21 * A2[k];
    }
  }

  // ---- t112: sym-packed (1,1,2) on A1⊗A1 ----
  {
    float pp[6] = {A1[0]*A1[0], A1[0]*A1[1], A1[0]*A1[2],
                   A1[1]*A1[1], A1[1]*A1[2], A1[2]*A1[2]};
    float t[5] = {0,0,0,0,0};
    c5sym<6>(s_cg, R112, pp, t);
    float u11 = W3(19), u20 = W3(20), u21 = W3(21);
#pragma unroll
    for (int k = 0; k < 5; k++) {
      S2_11[k] = fmaf(u11, t[k], S2_11[k]);
      S2_20[k] = fmaf(u20, t[k], S2_20[k]);
      S2_21[k] = fmaf(u21, t[k], S2_21[k]);
    }
  }
  // ---- t121 (== t211) ----
  {
    float t[3] = {0,0,0};
    c3acc<3,5>(s_cg, R121, A1, A2, t);
    float ub  = W2(5)  + W2(6);
    float u01 = W3(22) + W3(33);
    float u10 = W3(23) + W3(34);
    float u11 = W3(24) + W3(35);
    float u21 = W3(25) + W3(36);
#pragma unroll
    for (int k = 0; k < 3; k++) {
      B1[k]    = fmaf(ub,  t[k], B1[k]);
      S1_01[k] = fmaf(u01, t[k], S1_01[k]);
      S1_10[k] = fmaf(u10, t[k], S1_10[k]);
      S1_11[k] = fmaf(u11, t[k], S1_11[k]);
      S1_21[k] = fmaf(u21, t[k], S1_21[k]);
    }
  }
  // ---- t122 (t212 = -t122) ----
  {
    float t[5] = {0,0,0,0,0};
    c5acc<3,5>(s_cg, R122, A1, A2, t);
    float u11 = W3(26) - W3(37);
    float u20 = W3(27) - W3(38);
    float u21 = W3(28) - W3(39);
#pragma unroll
    for (int k = 0; k < 5; k++) {
      S2_11[k] = fmaf(u11, t[k], S2_11[k]);
      S2_20[k] = fmaf(u20, t[k], S2_20[k]);
      S2_21[k] = fmaf(u21, t[k], S2_21[k]);
    }
  }
  // ---- t123 (== t213): only feeder of S3_21 ----
  float S3_21[7];
  {
    float t[7] = {0,0,0,0,0,0,0};
    c7acc<3,5>(s_cg, R123, A1, A2, t);
    float u = W3(29) + W3(40);
#pragma unroll
    for (int k = 0; k < 7; k++) S3_21[k] = u * t[k];
  }
  // ---- t222: sym-packed (2,2,2) on A2⊗A2 ----
  {
    float qq[15];
    {
      int p = 0;
#pragma unroll
      for (int i = 0; i < 5; i++)
#pragma unroll
        for (int j = i; j < 5; j++) qq[p++] = A2[i] * A2[j];
    }
    float t[5] = {0,0,0,0,0};
    c5sym<15>(s_cg, R222, qq, t);
    float u11 = W3(47), u20 = W3(48), u21 = W3(49);
#pragma unroll
    for (int k = 0; k < 5; k++) {
      S2_11[k] = fmaf(u11, t[k], S2_11[k]);
      S2_20[k] = fmaf(u20, t[k], S2_20[k]);
      S2_21[k] = fmaf(u21, t[k], S2_21[k]);
    }
  }

  // ---- stage 2 ----
  B0 = fmaf(S0_00, A0, B0);                                 // (0,0,0), cg=1
#pragma unroll
  for (int k = 0; k < 3; k++) {
    B1[k] = fmaf(S0_11, A1[k], B1[k]);                      // (0,1,1) = δ
    B1[k] = fmaf(S1_01[k], A0, B1[k]);                      // (1,0,1) = δ
  }
  {                                                          // (1,1,0) = c·δ
    float d = fmaf(S1_10[2], A1[2], fmaf(S1_10[1], A1[1], S1_10[0]*A1[0]));
    B0 = fmaf(c110, d, B0);
  }
  {                                                          // (1,1,1) = c·eps
    float cx = fmaf(-S1_11[2], A1[1], S1_11[1]*A1[2]);
    float cy = fmaf(-S1_11[0], A1[2], S1_11[2]*A1[0]);
    float cz = fmaf(-S1_11[1], A1[0], S1_11[0]*A1[1]);
    B1[0] = fmaf(c111, cx, B1[0]);
    B1[1] = fmaf(c111, cy, B1[1]);
    B1[2] = fmaf(c111, cz, B1[2]);
  }
  c3acc<3,5>(s_cg, R121, S1_21, A2, B1);                    // (1,2,1)
  c3accT53(s_cg, R121, S2_11, A1, B1);                      // (2,1,1) = T121 transposed (+)
  {                                                          // (2,2,0) = c·δ
    float d = fmaf(S2_20[4], A2[4], fmaf(S2_20[3], A2[3],
               fmaf(S2_20[2], A2[2], fmaf(S2_20[1], A2[1], S2_20[0]*A2[0]))));
    B0 = fmaf(c220, d, B0);
  }
  c3acc<5,5>(s_cg, R221, S2_21, A2, B1);                    // (2,2,1)
  c3acc<7,5>(s_cg, R321, S3_21, A2, B1);                    // (3,2,1)

  g_B[(size_t)n * NCH + c] = make_float4(B0, B1[0], B1[1], B1[2]);
#undef W1
#undef W2
#undef W3
}

// ---------------------------------------------------------------------------
// Phase B: equivariant linear (scalar, round-1 form).
// ---------------------------------------------------------------------------
#define NODE_TILE 16
__global__ __launch_bounds__(128)
void phaseB_kernel(const float* __restrict__ lin_w0,
                   const float* __restrict__ lin_w1,
                   float* __restrict__ out) {
  __shared__ float4 sB[NODE_TILE * NCH];   // 32 KB
  const int n0 = blockIdx.x * NODE_TILE;
  const int f  = threadIdx.x;

  const float4* Bp = g_B + (size_t)n0 * NCH;
  for (int i = f; i < NODE_TILE * NCH; i += 128) sB[i] = Bp[i];
  __syncthreads();

  float acc[NODE_TILE][4];
#pragma unroll
  for (int nt = 0; nt < NODE_TILE; nt++)
#pragma unroll
    for (int m = 0; m < 4; m++) acc[nt][m] = 0.f;

  for (int cch = 0; cch < NCH; cch++) {
    float w0  = lin_w0[cch * NFEAT + f];
    float w1v = lin_w1[cch * NFEAT + f];
#pragma unroll
    for (int nt = 0; nt < NODE_TILE; nt++) {
      float4 b = sB[nt * NCH + cch];
      acc[nt][0] = fmaf(b.x, w0,  acc[nt][0]);
      acc[nt][1] = fmaf(b.y, w1v, acc[nt][1]);
      acc[nt][2] = fmaf(b.z, w1v, acc[nt][2]);
      acc[nt][3] = fmaf(b.w, w1v, acc[nt][3]);
    }
  }

  const float s = 0.08838834764831845f;  // 1/sqrt(128)
  float4* op = (float4*)out;
#pragma unroll
  for (int nt = 0; nt < NODE_TILE; nt++) {
    op[(size_t)(n0 + nt) * NFEAT + f] =
      make_float4(acc[nt][0] * s, acc[nt][1] * s, acc[nt][2] * s, acc[nt][3] * s);
  }
}

// ---------------------------------------------------------------------------
// Launch
// ---------------------------------------------------------------------------
extern "C" void kernel_launch(void* const* d_in, const int* in_sizes, int n_in,
                              void* d_out, int out_size) {
  const float* feats   = (const float*)d_in[0];  // [4096,128,9]
  const float* w1      = (const float*)d_in[1];  // [10,2,128]
  const float* w2      = (const float*)d_in[2];  // [10,9,128]
  const float* w3      = (const float*)d_in[3];  // [10,51,128]
  const float* lin_w0  = (const float*)d_in[4];  // [128,128]
  const float* lin_w1  = (const float*)d_in[5];  // [128,128]
  const int*   species = (const int*)d_in[6];    // [4096]

  cg_setup_kernel<<<8, 128>>>();
  phaseA_kernel<<<NNODES, 128>>>(feats, w1, w2, w3, species);
  phaseB_kernel<<<NNODES / NODE_TILE, 128>>>(lin_w0, lin_w1, (float*)d_out);
}

// round 4
// speedup vs baseline: 3.1189x; 1.5315x over previous
#include <cuda_runtime.h>
#include <math.h>

#define NNODES 4096
#define NCH    128
#define NELEM  10
#define NFEAT  128

__device__ float4 g_B[NNODES * NCH];   // per (node,channel): {B0, B1x, B1y, B1z}

// ===========================================================================
// Compile-time real Clebsch-Gordan coefficients (e3nn convention).
// All in double, mirrors the reference _su2_cg / _c2r / real_cg exactly.
// ===========================================================================
__host__ __device__ constexpr double cfact(int n) {
  double r = 1.0;
  for (int i = 2; i <= n; i++) r *= (double)i;
  return r;
}
__host__ __device__ constexpr double csqrt(double x) {
  if (x <= 0.0) return 0.0;
  double g = x > 1.0 ? x : 1.0;
  for (int i = 0; i < 64; i++) g = 0.5 * (g + x / g);
  return g;
}
__host__ __device__ constexpr double su2cg_ct(int j1,int m1,int j2,int m2,int j3,int m3) {
  if (m1 + m2 != m3) return 0.0;
  int vmin = -j1 + j2 + m3; if (-j1 + m1 > vmin) vmin = -j1 + m1; if (0 > vmin) vmin = 0;
  int vmax = j2 + j3 + m1; if (j3 - j1 + j2 < vmax) vmax = j3 - j1 + j2; if (j3 + m3 < vmax) vmax = j3 + m3;
  if (vmax < vmin) return 0.0;
  double C = csqrt((2.0*j3 + 1.0) * cfact(j3+j1-j2) * cfact(j3-j1+j2) * cfact(j1+j2-j3)
                   * cfact(j3+m3) * cfact(j3-m3)
                   / (cfact(j1+j2+j3+1) * cfact(j1-m1) * cfact(j1+m1)
                      * cfact(j2-m2) * cfact(j2+m2)));
  double S = 0.0;
  for (int v = vmin; v <= vmax; v++) {
    double t = cfact(j2+j3+m1-v) * cfact(j1-m1+v)
             / (cfact(v) * cfact(j3-j1+j2-v) * cfact(j3+m3-v) * cfact(v+j1-j2-m3));
    S += (((v + j2 + m2) & 1) != 0) ? -t : t;
  }
  return C * S;
}
struct cx { double re, im; };
__host__ __device__ constexpr cx c2r_ct(int l, int r, int c) {
  int m = r - l;
  double IS2 = 0.70710678118654752440;
  double re = 0.0, im = 0.0;
  if (m < 0) {
    if (c == l - m)      re = IS2;
    else if (c == l + m) im = -IS2;
  } else if (m == 0) {
    if (c == l) re = 1.0;
  } else {
    double s = ((m & 1) != 0) ? -1.0 : 1.0;
    if (c == l + m)      re = s * IS2;
    else if (c == l - m) im = s * IS2;
  }
  // multiply by (-i)^l
  double tr = 0.0;
  switch (l & 3) {
    case 1: tr = re; re = im;  im = -tr; break;
    case 2: re = -re; im = -im;          break;
    case 3: tr = re; re = -im; im = tr;  break;
    default: break;
  }
  return cx{re, im};
}
__host__ __device__ constexpr double rcg(int l1,int l2,int l3,int i,int j,int k) {
  double acc = 0.0;
  for (int i2 = 0; i2 < 2*l1+1; i2++)
    for (int k2 = 0; k2 < 2*l2+1; k2++) {
      int m1 = i2 - l1, m2 = k2 - l2, m3 = m1 + m2;
      if (m3 < -l3 || m3 > l3) continue;
      double cc = su2cg_ct(l1, m1, l2, m2, l3, m3);
      if (cc == 0.0) continue;
      cx q1 = c2r_ct(l1, i2, i);
      cx q2 = c2r_ct(l2, k2, j);
      cx q3 = c2r_ct(l3, m3 + l3, k);
      double pr = q1.re*q2.re - q1.im*q2.im;
      double pi = q1.re*q2.im + q1.im*q2.re;
      acc += cc * (pr * q3.re + pi * q3.im);
    }
  return acc;
}
__host__ __device__ constexpr double zclip(double x) {
  return (x > 1e-10 || x < -1e-10) ? x : 0.0;
}

// ---------------------------------------------------------------------------
// compile-time unrolled loops
// ---------------------------------------------------------------------------
template<int I> struct ic { static constexpr int v = I; };
template<int N, typename F>
__device__ __forceinline__ void sfor(F&& f) {
  if constexpr (N > 0) { sfor<N-1>((F&&)f); f(ic<N-1>{}); }
}

// t[k] += sum_{i,j} cg(L1,L2,L3)[i,j,k] * a[i]*b[j]  (coefficients = immediates)
// SYM: fold j>=i with doubling (valid when a==b)
template<int L1,int L2,int L3,bool SYM>
__device__ __forceinline__ void cgc(const float* a, const float* b, float* t) {
  sfor<2*L1+1>([&](auto I) {
    sfor<2*L2+1>([&](auto J) {
      constexpr int iv = decltype(I)::v, jv = decltype(J)::v;
      if constexpr (!SYM || jv >= iv) {
        const float p = a[iv] * b[jv];
        sfor<2*L3+1>([&](auto K) {
          constexpr int kv = decltype(K)::v;
          constexpr float cc =
            (float)zclip(rcg(L1,L2,L3,iv,jv,kv) * ((SYM && iv != jv) ? 2.0 : 1.0));
          if constexpr (cc != 0.f) t[kv] = fmaf(cc, p, t[kv]);
        });
      }
    });
  });
}

// ---------------------------------------------------------------------------
// Phase A: per (node,channel) product basis using symmetry-reduced paths.
// All CG coefficients are compile-time immediates; zero paths deleted.
// 2 nodes per block (256 threads).
// ---------------------------------------------------------------------------
__global__ __launch_bounds__(256)
void phaseA_kernel(const float* __restrict__ feats,
                   const float* __restrict__ w1,
                   const float* __restrict__ w2,
                   const float* __restrict__ w3,
                   const int*   __restrict__ species) {
  const int c = threadIdx.x & 127;
  const int n = blockIdx.x * 2 + (threadIdx.x >> 7);

  const int e = species[n];
  const float* fp = feats + ((size_t)n * NCH + c) * 9;
  float A[9];
#pragma unroll
  for (int k = 0; k < 9; k++) A[k] = fp[k];
  const float  A0 = A[0];
  const float* A1 = A + 1;
  const float* A2 = A + 4;

  const float* w1p = w1 + (size_t)(e * 2)  * NCH + c;
  const float* w2p = w2 + (size_t)(e * 9)  * NCH + c;
  const float* w3p = w3 + (size_t)(e * 51) * NCH + c;
#define W1(p) w1p[(p)*NCH]
#define W2(p) w2p[(p)*NCH]
#define W3(p) w3p[(p)*NCH]

  constexpr float c110 = (float)rcg(1,1,0, 0,0,0);
  constexpr float c220 = (float)rcg(2,2,0, 0,0,0);
  constexpr float c111 = (float)rcg(1,1,1, 0,1,2);

  // ---- order 1 ----
  float B0 = W1(0) * A0;
  float B1[3];
#pragma unroll
  for (int k = 0; k < 3; k++) B1[k] = W1(1) * A1[k];

  // ---- stage-1 scalars ----
  float t000 = A0 * A0;
  B0 = fmaf(W2(0), t000, B0);
  float S0_00 = W3(0) * t000;
  float S0_11 = W3(1) * t000;

  float d11 = fmaf(A1[2], A1[2], fmaf(A1[1], A1[1], A1[0]*A1[0]));
  float d22 = fmaf(A2[4], A2[4], fmaf(A2[3], A2[3],
               fmaf(A2[2], A2[2], fmaf(A2[1], A2[1], A2[0]*A2[0]))));
  float t110 = c110 * d11;               // cg(1,1,0) = c·δ
  B0    = fmaf(W2(3),  t110, B0);
  S0_00 = fmaf(W3(13), t110, S0_00);
  S0_11 = fmaf(W3(14), t110, S0_11);
  float t220 = c220 * d22;               // cg(2,2,0) = c·δ
  B0    = fmaf(W2(7),  t220, B0);
  S0_00 = fmaf(W3(41), t220, S0_00);
  S0_11 = fmaf(W3(42), t220, S0_11);

  // ---- t011 = A0*A1 (== t101) : δ couplings ----
  float S1_01[3], S1_10[3], S1_11[3], S1_21[3];
  {
    float u = (W2(1) + W2(2)) * A0;
#pragma unroll
    for (int k = 0; k < 3; k++) B1[k] = fmaf(u, A1[k], B1[k]);
    float u01 = (W3(2) + W3(9))  * A0;
    float u10 = (W3(3) + W3(10)) * A0;
    float u11 = (W3(4) + W3(11)) * A0;
    float u21 = (W3(5) + W3(12)) * A0;
#pragma unroll
    for (int k = 0; k < 3; k++) {
      S1_01[k] = u01 * A1[k];
      S1_10[k] = u10 * A1[k];
      S1_11[k] = u11 * A1[k];
      S1_21[k] = u21 * A1[k];
    }
  }
  // ---- t022 = A0*A2 (== t202) ----
  float S2_11[5], S2_20[5], S2_21[5];
  {
    float u11 = (W3(6) + W3(30)) * A0;
    float u20 = (W3(7) + W3(31)) * A0;
    float u21 = (W3(8) + W3(32)) * A0;
#pragma unroll
    for (int k = 0; k < 5; k++) {
      S2_11[k] = u11 * A2[k];
      S2_20[k] = u20 * A2[k];
      S2_21[k] = u21 * A2[k];
    }
  }

  // ---- t112: symmetric (1,1,2) on A1⊗A1 ----
  {
    float t[5] = {0,0,0,0,0};
    cgc<1,1,2,true>(A1, A1, t);
    float u11 = W3(19), u20 = W3(20), u21 = W3(21);
#pragma unroll
    for (int k = 0; k < 5; k++) {
      S2_11[k] = fmaf(u11, t[k], S2_11[k]);
      S2_20[k] = fmaf(u20, t[k], S2_20[k]);
      S2_21[k] = fmaf(u21, t[k], S2_21[k]);
    }
  }
  // ---- t121 (== t211) ----
  {
    float t[3] = {0,0,0};
    cgc<1,2,1,false>(A1, A2, t);
    float ub  = W2(5)  + W2(6);
    float u01 = W3(22) + W3(33);
    float u10 = W3(23) + W3(34);
    float u11 = W3(24) + W3(35);
    float u21 = W3(25) + W3(36);
#pragma unroll
    for (int k = 0; k < 3; k++) {
      B1[k]    = fmaf(ub,  t[k], B1[k]);
      S1_01[k] = fmaf(u01, t[k], S1_01[k]);
      S1_10[k] = fmaf(u10, t[k], S1_10[k]);
      S1_11[k] = fmaf(u11, t[k], S1_11[k]);
      S1_21[k] = fmaf(u21, t[k], S1_21[k]);
    }
  }
  // ---- t122 (t212 = -t122) ----
  {
    float t[5] = {0,0,0,0,0};
    cgc<1,2,2,false>(A1, A2, t);
    float u11 = W3(26) - W3(37);
    float u20 = W3(27) - W3(38);
    float u21 = W3(28) - W3(39);
#pragma unroll
    for (int k = 0; k < 5; k++) {
      S2_11[k] = fmaf(u11, t[k], S2_11[k]);
      S2_20[k] = fmaf(u20, t[k], S2_20[k]);
      S2_21[k] = fmaf(u21, t[k], S2_21[k]);
    }
  }
  // ---- t123 (== t213): only feeder of S3_21 ----
  float S3_21[7];
  {
    float t[7] = {0,0,0,0,0,0,0};
    cgc<1,2,3,false>(A1, A2, t);
    float u = W3(29) + W3(40);
#pragma unroll
    for (int k = 0; k < 7; k++) S3_21[k] = u * t[k];
  }
  // ---- t222: symmetric (2,2,2) on A2⊗A2 ----
  {
    float t[5] = {0,0,0,0,0};
    cgc<2,2,2,true>(A2, A2, t);
    float u11 = W3(47), u20 = W3(48), u21 = W3(49);
#pragma unroll
    for (int k = 0; k < 5; k++) {
      S2_11[k] = fmaf(u11, t[k], S2_11[k]);
      S2_20[k] = fmaf(u20, t[k], S2_20[k]);
      S2_21[k] = fmaf(u21, t[k], S2_21[k]);
    }
  }

  // ---- stage 2 ----
  B0 = fmaf(S0_00, A0, B0);                                 // (0,0,0), cg=1
#pragma unroll
  for (int k = 0; k < 3; k++) {
    B1[k] = fmaf(S0_11, A1[k], B1[k]);                      // (0,1,1) = δ
    B1[k] = fmaf(S1_01[k], A0, B1[k]);                      // (1,0,1) = δ
  }
  {                                                          // (1,1,0) = c·δ
    float d = fmaf(S1_10[2], A1[2], fmaf(S1_10[1], A1[1], S1_10[0]*A1[0]));
    B0 = fmaf(c110, d, B0);
  }
  {                                                          // (1,1,1) = c·eps
    float cxp = fmaf(-S1_11[2], A1[1], S1_11[1]*A1[2]);
    float cyp = fmaf(-S1_11[0], A1[2], S1_11[2]*A1[0]);
    float czp = fmaf(-S1_11[1], A1[0], S1_11[0]*A1[1]);
    B1[0] = fmaf(c111, cxp, B1[0]);
    B1[1] = fmaf(c111, cyp, B1[1]);
    B1[2] = fmaf(c111, czp, B1[2]);
  }
  cgc<1,2,1,false>(S1_21, A2, B1);                          // (1,2,1)
  cgc<2,1,1,false>(S2_11, A1, B1);                          // (2,1,1)
  {                                                          // (2,2,0) = c·δ
    float d = fmaf(S2_20[4], A2[4], fmaf(S2_20[3], A2[3],
               fmaf(S2_20[2], A2[2], fmaf(S2_20[1], A2[1], S2_20[0]*A2[0]))));
    B0 = fmaf(c220, d, B0);
  }
  cgc<2,2,1,false>(S2_21, A2, B1);                          // (2,2,1)
  cgc<3,2,1,false>(S3_21, A2, B1);                          // (3,2,1)

  g_B[(size_t)n * NCH + c] = make_float4(B0, B1[0], B1[1], B1[2]);
#undef W1
#undef W2
#undef W3
}

// ---------------------------------------------------------------------------
// Phase B: equivariant linear (scalar).
// ---------------------------------------------------------------------------
#define NODE_TILE 16
__global__ __launch_bounds__(128)
void phaseB_kernel(const float* __restrict__ lin_w0,
                   const float* __restrict__ lin_w1,
                   float* __restrict__ out) {
  __shared__ float4 sB[NODE_TILE * NCH];   // 32 KB
  const int n0 = blockIdx.x * NODE_TILE;
  const int f  = threadIdx.x;

  const float4* Bp = g_B + (size_t)n0 * NCH;
  for (int i = f; i < NODE_TILE * NCH; i += 128) sB[i] = Bp[i];
  __syncthreads();

  float acc[NODE_TILE][4];
#pragma unroll
  for (int nt = 0; nt < NODE_TILE; nt++)
#pragma unroll
    for (int m = 0; m < 4; m++) acc[nt][m] = 0.f;

  for (int cch = 0; cch < NCH; cch++) {
    float w0  = lin_w0[cch * NFEAT + f];
    float w1v = lin_w1[cch * NFEAT + f];
#pragma unroll
    for (int nt = 0; nt < NODE_TILE; nt++) {
      float4 b = sB[nt * NCH + cch];
      acc[nt][0] = fmaf(b.x, w0,  acc[nt][0]);
      acc[nt][1] = fmaf(b.y, w1v, acc[nt][1]);
      acc[nt][2] = fmaf(b.z, w1v, acc[nt][2]);
      acc[nt][3] = fmaf(b.w, w1v, acc[nt][3]);
    }
  }

  const float s = 0.08838834764831845f;  // 1/sqrt(128)
  float4* op = (float4*)out;
#pragma unroll
  for (int nt = 0; nt < NODE_TILE; nt++) {
    op[(size_t)(n0 + nt) * NFEAT + f] =
      make_float4(acc[nt][0] * s, acc[nt][1] * s, acc[nt][2] * s, acc[nt][3] * s);
  }
}

// ---------------------------------------------------------------------------
// Launch
// ---------------------------------------------------------------------------
extern "C" void kernel_launch(void* const* d_in, const int* in_sizes, int n_in,
                              void* d_out, int out_size) {
  const float* feats   = (const float*)d_in[0];  // [4096,128,9]
  const float* w1      = (const float*)d_in[1];  // [10,2,128]
  const float* w2      = (const float*)d_in[2];  // [10,9,128]
  const float* w3      = (const float*)d_in[3];  // [10,51,128]
  const float* lin_w0  = (const float*)d_in[4];  // [128,128]
  const float* lin_w1  = (const float*)d_in[5];  // [128,128]
  const int*   species = (const int*)d_in[6];    // [4096]

  phaseA_kernel<<<NNODES / 2, 256>>>(feats, w1, w2, w3, species);
  phaseB_kernel<<<NNODES / NODE_TILE, 128>>>(lin_w0, lin_w1, (float*)d_out);
}

// round 5
// speedup vs baseline: 4.7176x; 1.5126x over previous
#include <cuda_runtime.h>
#include <math.h>

#define NNODES 4096
#define NCH    128
#define NELEM  10
#define NFEAT  128

__device__ float4 g_B[NNODES * NCH];   // per (node,channel): {B0, B1x, B1y, B1z}

// ===========================================================================
// Compile-time real Clebsch-Gordan coefficients (e3nn convention).
// ===========================================================================
__host__ __device__ constexpr double cfact(int n) {
  double r = 1.0;
  for (int i = 2; i <= n; i++) r *= (double)i;
  return r;
}
__host__ __device__ constexpr double csqrt(double x) {
  if (x <= 0.0) return 0.0;
  double g = x > 1.0 ? x : 1.0;
  for (int i = 0; i < 64; i++) g = 0.5 * (g + x / g);
  return g;
}
__host__ __device__ constexpr double su2cg_ct(int j1,int m1,int j2,int m2,int j3,int m3) {
  if (m1 + m2 != m3) return 0.0;
  int vmin = -j1 + j2 + m3; if (-j1 + m1 > vmin) vmin = -j1 + m1; if (0 > vmin) vmin = 0;
  int vmax = j2 + j3 + m1; if (j3 - j1 + j2 < vmax) vmax = j3 - j1 + j2; if (j3 + m3 < vmax) vmax = j3 + m3;
  if (vmax < vmin) return 0.0;
  double C = csqrt((2.0*j3 + 1.0) * cfact(j3+j1-j2) * cfact(j3-j1+j2) * cfact(j1+j2-j3)
                   * cfact(j3+m3) * cfact(j3-m3)
                   / (cfact(j1+j2+j3+1) * cfact(j1-m1) * cfact(j1+m1)
                      * cfact(j2-m2) * cfact(j2+m2)));
  double S = 0.0;
  for (int v = vmin; v <= vmax; v++) {
    double t = cfact(j2+j3+m1-v) * cfact(j1-m1+v)
             / (cfact(v) * cfact(j3-j1+j2-v) * cfact(j3+m3-v) * cfact(v+j1-j2-m3));
    S += (((v + j2 + m2) & 1) != 0) ? -t : t;
  }
  return C * S;
}
struct cx { double re, im; };
__host__ __device__ constexpr cx c2r_ct(int l, int r, int c) {
  int m = r - l;
  double IS2 = 0.70710678118654752440;
  double re = 0.0, im = 0.0;
  if (m < 0) {
    if (c == l - m)      re = IS2;
    else if (c == l + m) im = -IS2;
  } else if (m == 0) {
    if (c == l) re = 1.0;
  } else {
    double s = ((m & 1) != 0) ? -1.0 : 1.0;
    if (c == l + m)      re = s * IS2;
    else if (c == l - m) im = s * IS2;
  }
  double tr = 0.0;
  switch (l & 3) {
    case 1: tr = re; re = im;  im = -tr; break;
    case 2: re = -re; im = -im;          break;
    case 3: tr = re; re = -im; im = tr;  break;
    default: break;
  }
  return cx{re, im};
}
__host__ __device__ constexpr double rcg(int l1,int l2,int l3,int i,int j,int k) {
  double acc = 0.0;
  for (int i2 = 0; i2 < 2*l1+1; i2++)
    for (int k2 = 0; k2 < 2*l2+1; k2++) {
      int m1 = i2 - l1, m2 = k2 - l2, m3 = m1 + m2;
      if (m3 < -l3 || m3 > l3) continue;
      double cc = su2cg_ct(l1, m1, l2, m2, l3, m3);
      if (cc == 0.0) continue;
      cx q1 = c2r_ct(l1, i2, i);
      cx q2 = c2r_ct(l2, k2, j);
      cx q3 = c2r_ct(l3, m3 + l3, k);
      double pr = q1.re*q2.re - q1.im*q2.im;
      double pi = q1.re*q2.im + q1.im*q2.re;
      acc += cc * (pr * q3.re + pi * q3.im);
    }
  return acc;
}
__host__ __device__ constexpr double zclip(double x) {
  return (x > 1e-10 || x < -1e-10) ? x : 0.0;
}

template<int I> struct ic { static constexpr int v = I; };
template<int N, typename F>
__device__ __forceinline__ void sfor(F&& f) {
  if constexpr (N > 0) { sfor<N-1>((F&&)f); f(ic<N-1>{}); }
}

template<int L1,int L2,int L3,bool SYM>
__device__ __forceinline__ void cgc(const float* a, const float* b, float* t) {
  sfor<2*L1+1>([&](auto I) {
    sfor<2*L2+1>([&](auto J) {
      constexpr int iv = decltype(I)::v, jv = decltype(J)::v;
      if constexpr (!SYM || jv >= iv) {
        const float p = a[iv] * b[jv];
        sfor<2*L3+1>([&](auto K) {
          constexpr int kv = decltype(K)::v;
          constexpr float cc =
            (float)zclip(rcg(L1,L2,L3,iv,jv,kv) * ((SYM && iv != jv) ? 2.0 : 1.0));
          if constexpr (cc != 0.f) t[kv] = fmaf(cc, p, t[kv]);
        });
      }
    });
  });
}

// ---------------------------------------------------------------------------
// Phase A (identical to round 4 — known good)
// ---------------------------------------------------------------------------
__global__ __launch_bounds__(256)
void phaseA_kernel(const float* __restrict__ feats,
                   const float* __restrict__ w1,
                   const float* __restrict__ w2,
                   const float* __restrict__ w3,
                   const int*   __restrict__ species) {
  const int c = threadIdx.x & 127;
  const int n = blockIdx.x * 2 + (threadIdx.x >> 7);

  const int e = species[n];
  const float* fp = feats + ((size_t)n * NCH + c) * 9;
  float A[9];
#pragma unroll
  for (int k = 0; k < 9; k++) A[k] = fp[k];
  const float  A0 = A[0];
  const float* A1 = A + 1;
  const float* A2 = A + 4;

  const float* w1p = w1 + (size_t)(e * 2)  * NCH + c;
  const float* w2p = w2 + (size_t)(e * 9)  * NCH + c;
  const float* w3p = w3 + (size_t)(e * 51) * NCH + c;
#define W1(p) w1p[(p)*NCH]
#define W2(p) w2p[(p)*NCH]
#define W3(p) w3p[(p)*NCH]

  constexpr float c110 = (float)rcg(1,1,0, 0,0,0);
  constexpr float c220 = (float)rcg(2,2,0, 0,0,0);
  constexpr float c111 = (float)rcg(1,1,1, 0,1,2);

  float B0 = W1(0) * A0;
  float B1[3];
#pragma unroll
  for (int k = 0; k < 3; k++) B1[k] = W1(1) * A1[k];

  float t000 = A0 * A0;
  B0 = fmaf(W2(0), t000, B0);
  float S0_00 = W3(0) * t000;
  float S0_11 = W3(1) * t000;

  float d11 = fmaf(A1[2], A1[2], fmaf(A1[1], A1[1], A1[0]*A1[0]));
  float d22 = fmaf(A2[4], A2[4], fmaf(A2[3], A2[3],
               fmaf(A2[2], A2[2], fmaf(A2[1], A2[1], A2[0]*A2[0]))));
  float t110 = c110 * d11;
  B0    = fmaf(W2(3),  t110, B0);
  S0_00 = fmaf(W3(13), t110, S0_00);
  S0_11 = fmaf(W3(14), t110, S0_11);
  float t220 = c220 * d22;
  B0    = fmaf(W2(7),  t220, B0);
  S0_00 = fmaf(W3(41), t220, S0_00);
  S0_11 = fmaf(W3(42), t220, S0_11);

  float S1_01[3], S1_10[3], S1_11[3], S1_21[3];
  {
    float u = (W2(1) + W2(2)) * A0;
#pragma unroll
    for (int k = 0; k < 3; k++) B1[k] = fmaf(u, A1[k], B1[k]);
    float u01 = (W3(2) + W3(9))  * A0;
    float u10 = (W3(3) + W3(10)) * A0;
    float u11 = (W3(4) + W3(11)) * A0;
    float u21 = (W3(5) + W3(12)) * A0;
#pragma unroll
    for (int k = 0; k < 3; k++) {
      S1_01[k] = u01 * A1[k];
      S1_10[k] = u10 * A1[k];
      S1_11[k] = u11 * A1[k];
      S1_21[k] = u21 * A1[k];
    }
  }
  float S2_11[5], S2_20[5], S2_21[5];
  {
    float u11 = (W3(6) + W3(30)) * A0;
    float u20 = (W3(7) + W3(31)) * A0;
    float u21 = (W3(8) + W3(32)) * A0;
#pragma unroll
    for (int k = 0; k < 5; k++) {
      S2_11[k] = u11 * A2[k];
      S2_20[k] = u20 * A2[k];
      S2_21[k] = u21 * A2[k];
    }
  }

  {
    float t[5] = {0,0,0,0,0};
    cgc<1,1,2,true>(A1, A1, t);
    float u11 = W3(19), u20 = W3(20), u21 = W3(21);
#pragma unroll
    for (int k = 0; k < 5; k++) {
      S2_11[k] = fmaf(u11, t[k], S2_11[k]);
      S2_20[k] = fmaf(u20, t[k], S2_20[k]);
      S2_21[k] = fmaf(u21, t[k], S2_21[k]);
    }
  }
  {
    float t[3] = {0,0,0};
    cgc<1,2,1,false>(A1, A2, t);
    float ub  = W2(5)  + W2(6);
    float u01 = W3(22) + W3(33);
    float u10 = W3(23) + W3(34);
    float u11 = W3(24) + W3(35);
    float u21 = W3(25) + W3(36);
#pragma unroll
    for (int k = 0; k < 3; k++) {
      B1[k]    = fmaf(ub,  t[k], B1[k]);
      S1_01[k] = fmaf(u01, t[k], S1_01[k]);
      S1_10[k] = fmaf(u10, t[k], S1_10[k]);
      S1_11[k] = fmaf(u11, t[k], S1_11[k]);
      S1_21[k] = fmaf(u21, t[k], S1_21[k]);
    }
  }
  {
    float t[5] = {0,0,0,0,0};
    cgc<1,2,2,false>(A1, A2, t);
    float u11 = W3(26) - W3(37);
    float u20 = W3(27) - W3(38);
    float u21 = W3(28) - W3(39);
#pragma unroll
    for (int k = 0; k < 5; k++) {
      S2_11[k] = fmaf(u11, t[k], S2_11[k]);
      S2_20[k] = fmaf(u20, t[k], S2_20[k]);
      S2_21[k] = fmaf(u21, t[k], S2_21[k]);
    }
  }
  float S3_21[7];
  {
    float t[7] = {0,0,0,0,0,0,0};
    cgc<1,2,3,false>(A1, A2, t);
    float u = W3(29) + W3(40);
#pragma unroll
    for (int k = 0; k < 7; k++) S3_21[k] = u * t[k];
  }
  {
    float t[5] = {0,0,0,0,0};
    cgc<2,2,2,true>(A2, A2, t);
    float u11 = W3(47), u20 = W3(48), u21 = W3(49);
#pragma unroll
    for (int k = 0; k < 5; k++) {
      S2_11[k] = fmaf(u11, t[k], S2_11[k]);
      S2_20[k] = fmaf(u20, t[k], S2_20[k]);
      S2_21[k] = fmaf(u21, t[k], S2_21[k]);
    }
  }

  B0 = fmaf(S0_00, A0, B0);
#pragma unroll
  for (int k = 0; k < 3; k++) {
    B1[k] = fmaf(S0_11, A1[k], B1[k]);
    B1[k] = fmaf(S1_01[k], A0, B1[k]);
  }
  {
    float d = fmaf(S1_10[2], A1[2], fmaf(S1_10[1], A1[1], S1_10[0]*A1[0]));
    B0 = fmaf(c110, d, B0);
  }
  {
    float cxp = fmaf(-S1_11[2], A1[1], S1_11[1]*A1[2]);
    float cyp = fmaf(-S1_11[0], A1[2], S1_11[2]*A1[0]);
    float czp = fmaf(-S1_11[1], A1[0], S1_11[0]*A1[1]);
    B1[0] = fmaf(c111, cxp, B1[0]);
    B1[1] = fmaf(c111, cyp, B1[1]);
    B1[2] = fmaf(c111, czp, B1[2]);
  }
  cgc<1,2,1,false>(S1_21, A2, B1);
  cgc<2,1,1,false>(S2_11, A1, B1);
  {
    float d = fmaf(S2_20[4], A2[4], fmaf(S2_20[3], A2[3],
               fmaf(S2_20[2], A2[2], fmaf(S2_20[1], A2[1], S2_20[0]*A2[0]))));
    B0 = fmaf(c220, d, B0);
  }
  cgc<2,2,1,false>(S2_21, A2, B1);
  cgc<3,2,1,false>(S3_21, A2, B1);

  g_B[(size_t)n * NCH + c] = make_float4(B0, B1[0], B1[1], B1[2]);
#undef W1
#undef W2
#undef W3
}

// ---------------------------------------------------------------------------
// Phase B: 3xTF32 tensor-core equivariant linear.
//   out[n,f,m] = s * sum_c X_m[n,c] * W_m[c,f],  W_0 = lin_w0, W_{1..3} = lin_w1
// Block: 32 nodes x 64 f x 4 m. 8 warps: warp w -> m = w>>1, node-sub = (w&1)*16.
// Warp tile: 16 nodes x 64 f = 8 m16n8k8 tiles, K-loop 16 steps, 3 mma/tile/step.
// ---------------------------------------------------------------------------
__device__ __forceinline__ unsigned tf32hi(float x) {
  unsigned r; asm("cvt.rna.tf32.f32 %0,%1;" : "=r"(r) : "f"(x)); return r;
}
__device__ __forceinline__ void mma8(float* c, unsigned a0, unsigned a1, unsigned a2,
                                     unsigned a3, unsigned b0, unsigned b1) {
  asm("mma.sync.aligned.m16n8k8.row.col.f32.tf32.tf32.f32 "
      "{%0,%1,%2,%3},{%4,%5,%6,%7},{%8,%9},{%0,%1,%2,%3};"
      : "+f"(c[0]), "+f"(c[1]), "+f"(c[2]), "+f"(c[3])
      : "r"(a0), "r"(a1), "r"(a2), "r"(a3), "r"(b0), "r"(b1));
}

#define SP 260   // smem row pitch in floats (64*4 + 4 pad)

__global__ __launch_bounds__(256)
void phaseB_kernel(const float* __restrict__ lin_w0,
                   const float* __restrict__ lin_w1,
                   float* __restrict__ out) {
  __shared__ float s_out[32 * SP];

  const int tid  = threadIdx.x;
  const int warp = tid >> 5, lane = tid & 31;
  const int m    = warp >> 1;
  const int nsub = (warp & 1) * 16;
  const int nbase = (blockIdx.x >> 1) * 32;
  const int fbase = (blockIdx.x & 1) * 64;
  const float* W = (m == 0) ? lin_w0 : lin_w1;

  const float* X = (const float*)g_B;        // element (n,c,m) at (n*128+c)*4 + m
  const int qr = lane >> 2;                   // 0..7
  const int qc = lane & 3;                    // 0..3
  const long ra = ((long)(nbase + nsub + qr) * 128) * 4 + m;      // row qr
  const long rb = ra + 8 * 128 * 4;                                // row qr+8

  float acc[8][4];
#pragma unroll
  for (int t = 0; t < 8; t++)
#pragma unroll
    for (int k = 0; k < 4; k++) acc[t][k] = 0.f;

  for (int kk = 0; kk < 16; kk++) {
    const int k0 = kk * 8;
    // A fragments (rows = nodes, cols = channel k0..k0+7)
    float a0f = X[ra + (k0 + qc) * 4];
    float a1f = X[rb + (k0 + qc) * 4];
    float a2f = X[ra + (k0 + qc + 4) * 4];
    float a3f = X[rb + (k0 + qc + 4) * 4];
    unsigned ah0 = tf32hi(a0f), ah1 = tf32hi(a1f), ah2 = tf32hi(a2f), ah3 = tf32hi(a3f);
    unsigned al0 = tf32hi(a0f - __uint_as_float(ah0));
    unsigned al1 = tf32hi(a1f - __uint_as_float(ah1));
    unsigned al2 = tf32hi(a2f - __uint_as_float(ah2));
    unsigned al3 = tf32hi(a3f - __uint_as_float(ah3));

    const float* Wk0 = W + (k0 + qc) * NFEAT + fbase + qr;
    const float* Wk4 = W + (k0 + qc + 4) * NFEAT + fbase + qr;
#pragma unroll
    for (int t = 0; t < 8; t++) {
      float b0f = Wk0[t * 8];
      float b1f = Wk4[t * 8];
      unsigned bh0 = tf32hi(b0f), bh1 = tf32hi(b1f);
      unsigned bl0 = tf32hi(b0f - __uint_as_float(bh0));
      unsigned bl1 = tf32hi(b1f - __uint_as_float(bh1));
      mma8(acc[t], ah0, ah1, ah2, ah3, bh0, bh1);   // hi*hi
      mma8(acc[t], ah0, ah1, ah2, ah3, bl0, bl1);   // hi*lo
      mma8(acc[t], al0, al1, al2, al3, bh0, bh1);   // lo*hi
    }
  }

  // stage into smem as [node_local][f_local][m]
#pragma unroll
  for (int t = 0; t < 8; t++) {
    int fl = t * 8 + qc * 2;
    int r0 = (nsub + qr) * SP;
    int r8 = (nsub + qr + 8) * SP;
    s_out[r0 + fl * 4 + m]       = acc[t][0];
    s_out[r0 + (fl + 1) * 4 + m] = acc[t][1];
    s_out[r8 + fl * 4 + m]       = acc[t][2];
    s_out[r8 + (fl + 1) * 4 + m] = acc[t][3];
  }
  __syncthreads();

  const float s = 0.08838834764831845f;  // 1/sqrt(128)
  float4* op = (float4*)out;
#pragma unroll
  for (int i = 0; i < 8; i++) {
    int idx = tid + i * 256;
    int nl = idx >> 6, fl = idx & 63;
    float4 v = *(const float4*)&s_out[nl * SP + fl * 4];
    v.x *= s; v.y *= s; v.z *= s; v.w *= s;
    op[(size_t)(nbase + nl) * NFEAT + fbase + fl] = v;
  }
}

// ---------------------------------------------------------------------------
// Launch
// ---------------------------------------------------------------------------
extern "C" void kernel_launch(void* const* d_in, const int* in_sizes, int n_in,
                              void* d_out, int out_size) {
  const float* feats   = (const float*)d_in[0];  // [4096,128,9]
  const float* w1      = (const float*)d_in[1];  // [10,2,128]
  const float* w2      = (const float*)d_in[2];  // [10,9,128]
  const float* w3      = (const float*)d_in[3];  // [10,51,128]
  const float* lin_w0  = (const float*)d_in[4];  // [128,128]
  const float* lin_w1  = (const float*)d_in[5];  // [128,128]
  const int*   species = (const int*)d_in[6];    // [4096]

  phaseA_kernel<<<NNODES / 2, 256>>>(feats, w1, w2, w3, species);
  phaseB_kernel<<<NNODES / 32 * 2, 256>>>(lin_w0, lin_w1, (float*)d_out);
}